// round 9
// baseline (speedup 1.0000x reference)
#include <cuda_runtime.h>
#include <math.h>
#include <stdint.h>

// ---------------- problem constants ----------------
#define B_   32
#define S_   512
#define D_   768
#define H_   12
#define DH   64
#define E_   8
#define DFF  3072
#define T_   (B_*S_)        // 16384 tokens
#define NQKV (3*D_)         // 2304

#define MAX_ROWS (2*T_ + E_*128)   // 33792 padded MoE assignment rows
#define MAX_TILES (MAX_ROWS/128)   // 264

// ---------------- device scratch (static globals; no allocs) ----------------
__device__ float g_x2[T_*D_];
__device__ float g_qkv[T_*NQKV];
__device__ float g_scores[B_*H_*S_*S_];
__device__ float g_ao[T_*D_];
__device__ float g_xm[T_*D_];     // LN2 out, FULL fp32 (router input)
__device__ float g_xmr[T_*D_];    // LN2 out, tf32-rounded (MoE GEMM1 A)
__device__ float g_h[MAX_ROWS*DFF];
__device__ float g_y[MAX_ROWS*D_];
__device__ int   g_topi[T_*2];
__device__ float g_topw[T_*2];
__device__ int   g_cnt[E_];
__device__ int   g_off[E_+1];
__device__ int   g_cursor[E_];
__device__ int   g_rowidx[MAX_ROWS];
__device__ float g_rowwt[MAX_ROWS];
__device__ int   g_slot[T_*2];
__device__ int   g_tile_e[MAX_TILES];

// tf32-rounded weights, K-major [N][K] fp32
__device__ __align__(16) float g_qkvw[NQKV*D_];
__device__ __align__(16) float g_ow[D_*D_];
__device__ __align__(16) float g_w1t[E_*DFF*D_];
__device__ __align__(16) float g_w2t[E_*D_*DFF];

// ---------------- helpers ----------------
__device__ __forceinline__ unsigned f2tf32(float x) {
    unsigned u;
    asm("cvt.rna.tf32.f32 %0, %1;" : "=r"(u) : "f"(x));
    return u;
}
__device__ __forceinline__ float roundtf(float x) { return __uint_as_float(f2tf32(x)); }

__device__ __forceinline__ uint32_t smem_u32(const void* p) {
    uint32_t a;
    asm("{ .reg .u64 t; cvta.to.shared.u64 t, %1; cvt.u32.u64 %0, t; }" : "=r"(a) : "l"(p));
    return a;
}
__device__ __forceinline__ void mma_tf32(float c[4], const unsigned a[4], const unsigned b[2]) {
    asm volatile(
        "mma.sync.aligned.m16n8k8.row.col.f32.tf32.tf32.f32 "
        "{%0,%1,%2,%3}, {%4,%5,%6,%7}, {%8,%9}, {%0,%1,%2,%3};"
        : "+f"(c[0]), "+f"(c[1]), "+f"(c[2]), "+f"(c[3])
        : "r"(a[0]), "r"(a[1]), "r"(a[2]), "r"(a[3]), "r"(b[0]), "r"(b[1]));
}
__device__ __forceinline__ void cp16(uint32_t dst, const void* src) {
    asm volatile("cp.async.cg.shared.global [%0], [%1], 16;" :: "r"(dst), "l"(src) : "memory");
}
__device__ __forceinline__ void cp16z(uint32_t dst, const void* src, int sz) {
    asm volatile("cp.async.cg.shared.global [%0], [%1], 16, %2;" :: "r"(dst), "l"(src), "r"(sz) : "memory");
}

// =====================================================================
// cp.async-pipelined tf32 GEMM: C[M,N] = A[M,K] @ B[N,K]^T
// Tile 128x256, BK=16, 4 stages, 256 threads, warp tile 64x64.
// Inputs are pre-rounded to tf32 (no in-loop cvt).
// smem per stage: A 128 rows x 20 floats, B 256 rows x 20 floats.
// EPI: 0 +bias | 1 +bias+resid | 2 +bias,GELU,round
// =====================================================================
#define CA_STAGE_FLOATS 7680
#define CA_SMEM (4*CA_STAGE_FLOATS*4)   // 122880 bytes

template<bool MOE, bool GATHER, int EPI>
__global__ void __launch_bounds__(256, 1) ca_gemm(
    const float* __restrict__ A, int lda,
    const float* __restrict__ Bw, long long bstride,
    const float* __restrict__ biasb, int biasstride,
    const float* __restrict__ resid, float* __restrict__ C, int ldc, int K)
{
    if (MOE) {
        int e = g_tile_e[blockIdx.y];
        if (e < 0) return;
        Bw    += (long long)e * bstride;
        biasb += (long long)e * biasstride;
    }
    extern __shared__ float sm[];
    uint32_t smb = smem_u32(sm);
    int tid = threadIdx.x, lane = tid & 31, wid = tid >> 5;
    int gid = lane >> 2, tig = lane & 3, wm = wid & 1, wn = wid >> 1;
    int m0 = blockIdx.y * 128, n0 = blockIdx.x * 256;

    // A loader: row am = tid>>1, two 16B chunks at kq = (tid&1)*2 + {0,1}
    int am = tid >> 1, akq = (tid & 1) * 2;
    long long arow = GATHER ? (long long)g_rowidx[m0 + am] : (long long)(m0 + am);
    int asz = (GATHER && arow < 0) ? 0 : 16;
    const float* abase = A + (arow < 0 ? 0 : arow) * (long long)lda + akq * 4;
    // B loader: row n0+tid, 4 chunks of 16B
    const float* bbase = Bw + (long long)(n0 + tid) * K;
    uint32_t adst0 = smb + (uint32_t)(am * 80 + akq * 16);
    uint32_t bdst0 = smb + 10240u + (uint32_t)tid * 80u;

    int niter = K / 16;

    auto fill = [&](int c) {
        uint32_t so = (uint32_t)(c & 3) * 30720u;
        const float* as = abase + c * 16;
        cp16z(adst0 + so,      as,     asz);
        cp16z(adst0 + so + 16, as + 4, asz);
        const float* bs = bbase + c * 16;
#pragma unroll
        for (int q = 0; q < 4; q++) cp16(bdst0 + so + q * 16, bs + q * 4);
        asm volatile("cp.async.commit_group;" ::: "memory");
    };

    fill(0); fill(1); fill(2);

    float acc[4][8][4];
#pragma unroll
    for (int i = 0; i < 4; i++)
#pragma unroll
        for (int j = 0; j < 8; j++)
#pragma unroll
            for (int q = 0; q < 4; q++) acc[i][j][q] = 0.f;

    unsigned af[2][4][4], bf[2][8][2];

    for (int c = 0; c < niter; c++) {
        asm volatile("cp.async.wait_group 2;" ::: "memory");
        __syncthreads();
        if (c + 3 < niter) {
            fill(c + 3);
        } else {
            // empty group keeps the committed-count invariant so wait_group 2
            // at iteration c always covers stage c
            asm volatile("cp.async.commit_group;" ::: "memory");
        }

        const float* Sa = sm + (size_t)(c & 3) * CA_STAGE_FLOATS;
        const float* Sb = Sa + 2560;

#pragma unroll
        for (int h = 0; h < 2; h++) {
            int ks = h * 8;
#pragma unroll
            for (int i = 0; i < 4; i++) {
                int r = wm * 64 + i * 16 + gid;
                af[h][i][0] = __float_as_uint(Sa[r * 20 + ks + tig]);
                af[h][i][1] = __float_as_uint(Sa[(r + 8) * 20 + ks + tig]);
                af[h][i][2] = __float_as_uint(Sa[r * 20 + ks + tig + 4]);
                af[h][i][3] = __float_as_uint(Sa[(r + 8) * 20 + ks + tig + 4]);
            }
#pragma unroll
            for (int j = 0; j < 8; j++) {
                int n = wn * 64 + j * 8 + gid;
                bf[h][j][0] = __float_as_uint(Sb[n * 20 + ks + tig]);
                bf[h][j][1] = __float_as_uint(Sb[n * 20 + ks + tig + 4]);
            }
        }
#pragma unroll
        for (int h = 0; h < 2; h++)
#pragma unroll
            for (int i = 0; i < 4; i++)
#pragma unroll
                for (int j = 0; j < 8; j++)
                    mma_tf32(acc[i][j], af[h][i], bf[h][j]);
    }

    // epilogue
#pragma unroll
    for (int i = 0; i < 4; i++) {
        long long r0 = m0 + wm * 64 + i * 16 + gid;
        long long r1 = r0 + 8;
#pragma unroll
        for (int j = 0; j < 8; j++) {
            int cc = n0 + wn * 64 + j * 8 + 2 * tig;
            float b0 = biasb[cc], b1 = biasb[cc + 1];
            float v00 = acc[i][j][0] + b0, v01 = acc[i][j][1] + b1;
            float v10 = acc[i][j][2] + b0, v11 = acc[i][j][3] + b1;
            if (EPI == 1) {
                v00 += resid[r0 * ldc + cc]; v01 += resid[r0 * ldc + cc + 1];
                v10 += resid[r1 * ldc + cc]; v11 += resid[r1 * ldc + cc + 1];
            }
            if (EPI == 2) {
                v00 = roundtf(0.5f * v00 * (1.f + erff(v00 * 0.70710678118654752f)));
                v01 = roundtf(0.5f * v01 * (1.f + erff(v01 * 0.70710678118654752f)));
                v10 = roundtf(0.5f * v10 * (1.f + erff(v10 * 0.70710678118654752f)));
                v11 = roundtf(0.5f * v11 * (1.f + erff(v11 * 0.70710678118654752f)));
            }
            C[r0 * ldc + cc]     = v00; C[r0 * ldc + cc + 1] = v01;
            C[r1 * ldc + cc]     = v10; C[r1 * ldc + cc + 1] = v11;
        }
    }
}

// ---------------- weight preprocessing (round to tf32) ----------------
__global__ void round_kernel(const float* __restrict__ w, float* __restrict__ o, int n) {
    int i = blockIdx.x * 256 + threadIdx.x;
    if (i < n) o[i] = roundtf(w[i]);
}
// transpose [e][R][C] fp32 -> [e][C][R] fp32 rounded
__global__ void tround_kernel(const float* __restrict__ w, float* __restrict__ o, int R, int C) {
    __shared__ float t[32][33];
    int e = blockIdx.z;
    int r0 = blockIdx.y * 32, c0 = blockIdx.x * 32;
    const float* we = w + (size_t)e * R * C;
    int x = threadIdx.x, y = threadIdx.y;
#pragma unroll
    for (int i = 0; i < 32; i += 8)
        t[y + i][x] = we[(size_t)(r0 + y + i) * C + c0 + x];
    __syncthreads();
    size_t base = (size_t)e * R * C;
#pragma unroll
    for (int i = 0; i < 32; i += 8)
        o[base + (size_t)(c0 + y + i) * R + r0 + x] = roundtf(t[x][y + i]);
}

// ---------------- LayerNorm ----------------
// DUAL=false: out = tf32-rounded LN
// DUAL=true:  out = FULL-precision LN (router input), out_r = tf32-rounded copy
template<bool DUAL>
__global__ void ln_kernel(const float* __restrict__ x, const float* __restrict__ gam,
                          const float* __restrict__ bet, float* __restrict__ out,
                          float* __restrict__ out_r) {
    int row = blockIdx.x;
    const float* xr = x + (size_t)row * D_;
    float v[3];
    float s = 0.f, s2 = 0.f;
#pragma unroll
    for (int i = 0; i < 3; i++) {
        v[i] = xr[threadIdx.x + i*256];
        s += v[i]; s2 += v[i]*v[i];
    }
    __shared__ float sh[16];
#pragma unroll
    for (int o = 16; o > 0; o >>= 1) {
        s  += __shfl_down_sync(0xffffffffu, s,  o);
        s2 += __shfl_down_sync(0xffffffffu, s2, o);
    }
    int w = threadIdx.x >> 5, l = threadIdx.x & 31;
    if (l == 0) { sh[w] = s; sh[w+8] = s2; }
    __syncthreads();
    if (threadIdx.x < 32) {
        float a  = (l < 8) ? sh[l]   : 0.f;
        float b2 = (l < 8) ? sh[l+8] : 0.f;
#pragma unroll
        for (int o = 4; o > 0; o >>= 1) {
            a  += __shfl_down_sync(0xffffffffu, a,  o);
            b2 += __shfl_down_sync(0xffffffffu, b2, o);
        }
        if (l == 0) { sh[0] = a; sh[1] = b2; }
    }
    __syncthreads();
    float mean = sh[0] * (1.f/D_);
    float var  = sh[1] * (1.f/D_) - mean*mean;
    float inv  = rsqrtf(var + 1e-5f);
#pragma unroll
    for (int i = 0; i < 3; i++) {
        int c = threadIdx.x + i*256;
        float r = (v[i] - mean) * inv * gam[c] + bet[c];
        if (DUAL) {
            out[(size_t)row*D_ + c]   = r;            // full precision for router
            out_r[(size_t)row*D_ + c] = roundtf(r);   // rounded for GEMM A
        } else {
            out[(size_t)row*D_ + c] = roundtf(r);
        }
    }
}

// ---------------- mma.sync tf32 attention GEMMs ----------------
template<int BN, bool BNK, int EPI, int ATT>   // EPI: 3 *scale | 4 plain+round
__global__ void __launch_bounds__(256) mma_gemm(
    const float* __restrict__ A, int lda,
    const float* __restrict__ Bb, int ldb,
    float* __restrict__ C, int ldc, int K, float scale)
{
    constexpr int WN  = BN / 4;
    constexpr int WNT = WN / 8;
    constexpr int LDA_S = 132;
    constexpr int LDB_S = BN + 4;

    __shared__ __align__(16) unsigned As[2][16][LDA_S];
    __shared__ __align__(16) unsigned Bs[2][16][LDB_S];

    int tid  = threadIdx.x;
    int lane = tid & 31, w = tid >> 5;
    int gid  = lane >> 2, tig = lane & 3;
    int wm   = w & 1, wn = w >> 1;
    int m0   = blockIdx.y * 128, n0 = blockIdx.x * BN;

    if (ATT == 1) {
        int z = blockIdx.z, b = z / H_, h = z % H_;
        A  += (size_t)(b * S_) * NQKV + h * DH;
        Bb += (size_t)(b * S_) * NQKV + D_ + h * DH;
        C  += (size_t)z * S_ * S_;
    }
    if (ATT == 2) {
        int z = blockIdx.z, b = z / H_, h = z % H_;
        A  += (size_t)z * S_ * S_;
        Bb += (size_t)(b * S_) * NQKV + 2 * D_ + h * DH;
        C  += (size_t)(b * S_) * D_ + h * DH;
    }

    int ar0 = tid >> 2, ak0 = (tid & 3) * 4;
    long long arow0 = m0 + ar0, arow1 = m0 + ar0 + 64;

    int bn0_t, bk0_t;
    if (BNK) { bn0_t = tid >> 2;        bk0_t = (tid & 3) * 4; }
    else     { bk0_t = tid / (BN / 4);  bn0_t = (tid % (BN / 4)) * 4; }
    constexpr int BCNT = BN / 64;

    float4 rA0, rA1, rB0, rB1;

    auto loadA = [&](int k0) {
        rA0 = *(const float4*)(A + arow0 * (long long)lda + k0 + ak0);
        rA1 = *(const float4*)(A + arow1 * (long long)lda + k0 + ak0);
    };
    auto stsA = [&](int buf) {
        As[buf][ak0+0][ar0] = f2tf32(rA0.x); As[buf][ak0+1][ar0] = f2tf32(rA0.y);
        As[buf][ak0+2][ar0] = f2tf32(rA0.z); As[buf][ak0+3][ar0] = f2tf32(rA0.w);
        As[buf][ak0+0][ar0+64] = f2tf32(rA1.x); As[buf][ak0+1][ar0+64] = f2tf32(rA1.y);
        As[buf][ak0+2][ar0+64] = f2tf32(rA1.z); As[buf][ak0+3][ar0+64] = f2tf32(rA1.w);
    };
    auto loadB = [&](int k0) {
        if (BNK) {
            rB0 = *(const float4*)(Bb + (long long)(n0 + bn0_t) * ldb + k0 + bk0_t);
            rB1 = *(const float4*)(Bb + (long long)(n0 + bn0_t + 64) * ldb + k0 + bk0_t);
        } else {
            rB0 = *(const float4*)(Bb + (long long)(k0 + bk0_t) * ldb + n0 + bn0_t);
            if (BCNT == 2)
                rB1 = *(const float4*)(Bb + (long long)(k0 + bk0_t + 8) * ldb + n0 + bn0_t);
        }
    };
    auto stsB = [&](int buf) {
        if (BNK) {
            Bs[buf][bk0_t+0][bn0_t] = f2tf32(rB0.x); Bs[buf][bk0_t+1][bn0_t] = f2tf32(rB0.y);
            Bs[buf][bk0_t+2][bn0_t] = f2tf32(rB0.z); Bs[buf][bk0_t+3][bn0_t] = f2tf32(rB0.w);
            Bs[buf][bk0_t+0][bn0_t+64] = f2tf32(rB1.x); Bs[buf][bk0_t+1][bn0_t+64] = f2tf32(rB1.y);
            Bs[buf][bk0_t+2][bn0_t+64] = f2tf32(rB1.z); Bs[buf][bk0_t+3][bn0_t+64] = f2tf32(rB1.w);
        } else {
            uint4 u0; u0.x = f2tf32(rB0.x); u0.y = f2tf32(rB0.y); u0.z = f2tf32(rB0.z); u0.w = f2tf32(rB0.w);
            *(uint4*)&Bs[buf][bk0_t][bn0_t] = u0;
            if (BCNT == 2) {
                uint4 u1; u1.x = f2tf32(rB1.x); u1.y = f2tf32(rB1.y); u1.z = f2tf32(rB1.z); u1.w = f2tf32(rB1.w);
                *(uint4*)&Bs[buf][bk0_t+8][bn0_t] = u1;
            }
        }
    };

    float acc[4][WNT][4];
#pragma unroll
    for (int i = 0; i < 4; i++)
#pragma unroll
        for (int j = 0; j < WNT; j++)
#pragma unroll
            for (int q = 0; q < 4; q++) acc[i][j][q] = 0.f;

    int niter = K / 16;
    loadA(0); loadB(0);
    stsA(0);  stsB(0);
    __syncthreads();

    for (int it = 0; it < niter; it++) {
        int buf = it & 1;
        if (it + 1 < niter) { loadA((it+1)*16); loadB((it+1)*16); }

#pragma unroll
        for (int ks = 0; ks < 16; ks += 8) {
            unsigned af[4][4];
#pragma unroll
            for (int i = 0; i < 4; i++) {
                int m = wm*64 + i*16 + gid;
                af[i][0] = As[buf][ks+tig  ][m];
                af[i][1] = As[buf][ks+tig  ][m+8];
                af[i][2] = As[buf][ks+tig+4][m];
                af[i][3] = As[buf][ks+tig+4][m+8];
            }
            unsigned bfg[WNT][2];
#pragma unroll
            for (int j = 0; j < WNT; j++) {
                int n = wn*WN + j*8 + gid;
                bfg[j][0] = Bs[buf][ks+tig  ][n];
                bfg[j][1] = Bs[buf][ks+tig+4][n];
            }
#pragma unroll
            for (int i = 0; i < 4; i++)
#pragma unroll
                for (int j = 0; j < WNT; j++)
                    mma_tf32(acc[i][j], af[i], bfg[j]);
        }

        if (it + 1 < niter) {
            stsA(buf ^ 1); stsB(buf ^ 1);
            __syncthreads();
        }
    }

#pragma unroll
    for (int i = 0; i < 4; i++) {
        long long r0 = m0 + wm*64 + i*16 + gid;
        long long r1 = r0 + 8;
#pragma unroll
        for (int j = 0; j < WNT; j++) {
            int c = n0 + wn*WN + j*8 + 2*tig;
            float v00 = acc[i][j][0], v01 = acc[i][j][1];
            float v10 = acc[i][j][2], v11 = acc[i][j][3];
            if (EPI == 3) { v00 *= scale; v01 *= scale; v10 *= scale; v11 *= scale; }
            if (EPI == 4) { v00 = roundtf(v00); v01 = roundtf(v01); v10 = roundtf(v10); v11 = roundtf(v11); }
            C[r0*ldc + c]   = v00; C[r0*ldc + c+1] = v01;
            C[r1*ldc + c]   = v10; C[r1*ldc + c+1] = v11;
        }
    }
}

// ---------------- softmax over last axis (512), block per row ----------------
__global__ void softmax_kernel(float* __restrict__ scores)
{
    size_t row = blockIdx.x;
    float* p = scores + row * S_;
    int tid = threadIdx.x;  // 128
    float v[4];
    float m = -1e30f;
#pragma unroll
    for (int i = 0; i < 4; i++) { v[i] = p[tid + i*128]; m = fmaxf(m, v[i]); }
    __shared__ float sm[4];
#pragma unroll
    for (int o = 16; o > 0; o >>= 1) m = fmaxf(m, __shfl_xor_sync(0xffffffffu, m, o));
    if ((tid & 31) == 0) sm[tid >> 5] = m;
    __syncthreads();
    m = fmaxf(fmaxf(sm[0], sm[1]), fmaxf(sm[2], sm[3]));
    float s = 0.f;
#pragma unroll
    for (int i = 0; i < 4; i++) { v[i] = __expf(v[i] - m); s += v[i]; }
#pragma unroll
    for (int o = 16; o > 0; o >>= 1) s += __shfl_xor_sync(0xffffffffu, s, o);
    __shared__ float ss[4];
    if ((tid & 31) == 0) ss[tid >> 5] = s;
    __syncthreads();
    s = ss[0] + ss[1] + ss[2] + ss[3];
    float inv = 1.f / s;
#pragma unroll
    for (int i = 0; i < 4; i++) p[tid + i*128] = v[i] * inv;
}

// ---------------- MoE routing ----------------
__global__ void moe_init_kernel() {
    int i = blockIdx.x * blockDim.x + threadIdx.x;
    if (i < E_) g_cnt[i] = 0;
    if (i < MAX_ROWS) g_rowidx[i] = -1;
}

__global__ void router_kernel(const float* __restrict__ xm, const float* __restrict__ rw,
                              const float* __restrict__ rb)
{
    int t = blockIdx.x;
    int w = threadIdx.x >> 5, l = threadIdx.x & 31;
    const float* xr = xm + (size_t)t * D_;
    const float* wr = rw + (size_t)w * D_;
    float s = 0.f;
    for (int d = l; d < D_; d += 32) s += xr[d] * wr[d];
#pragma unroll
    for (int o = 16; o > 0; o >>= 1) s += __shfl_down_sync(0xffffffffu, s, o);
    __shared__ float sh[E_];
    if (l == 0) sh[w] = s + rb[w];
    __syncthreads();
    if (threadIdx.x == 0) {
        int e1 = 0; float l1 = sh[0];
        for (int e = 1; e < E_; e++) if (sh[e] > l1) { l1 = sh[e]; e1 = e; }
        int e2 = -1; float l2 = -1e30f;
        for (int e = 0; e < E_; e++) if (e != e1 && sh[e] > l2) { l2 = sh[e]; e2 = e; }
        float w1 = 1.f / (1.f + __expf(l2 - l1));
        g_topi[2*t] = e1; g_topi[2*t+1] = e2;
        g_topw[2*t] = w1; g_topw[2*t+1] = 1.f - w1;
        atomicAdd(&g_cnt[e1], 1);
        atomicAdd(&g_cnt[e2], 1);
    }
}

__global__ void scan_kernel() {
    if (threadIdx.x == 0) {
        int o = 0;
        for (int e = 0; e < E_; e++) {
            g_off[e] = o; g_cursor[e] = o;
            o += ((g_cnt[e] + 127) >> 7) << 7;
        }
        g_off[E_] = o;
    }
    __syncthreads();
    for (int t = threadIdx.x; t < MAX_TILES; t += blockDim.x) {
        int row = t << 7;
        int e = -1;
        for (int ee = 0; ee < E_; ee++)
            if (row >= g_off[ee] && row < g_off[ee+1]) e = ee;
        g_tile_e[t] = (row < g_off[E_]) ? e : -1;
    }
}

__global__ void assign_kernel() {
    int t = blockIdx.x * blockDim.x + threadIdx.x;
    if (t >= T_) return;
#pragma unroll
    for (int k = 0; k < 2; k++) {
        int e = g_topi[2*t + k];
        int pos = atomicAdd(&g_cursor[e], 1);
        g_rowidx[pos] = t;
        g_rowwt[pos]  = g_topw[2*t + k];
        g_slot[2*t + k] = pos;
    }
}

__global__ void combine_kernel(float* __restrict__ out) {
    int i = blockIdx.x * blockDim.x + threadIdx.x;
    int t = i / D_;
    int d = i - t * D_;
    int s0 = g_slot[2*t], s1 = g_slot[2*t + 1];
    out[i] += g_rowwt[s0] * g_y[(size_t)s0 * D_ + d]
            + g_rowwt[s1] * g_y[(size_t)s1 * D_ + d];
}

// ---------------- launch ----------------
extern "C" void kernel_launch(void* const* d_in, const int* in_sizes, int n_in,
                              void* d_out, int out_size)
{
    const float* x          = (const float*)d_in[0];
    const float* ln1_g      = (const float*)d_in[1];
    const float* ln1_b      = (const float*)d_in[2];
    const float* in_proj_w  = (const float*)d_in[3];
    const float* in_proj_b  = (const float*)d_in[4];
    const float* out_proj_w = (const float*)d_in[5];
    const float* out_proj_b = (const float*)d_in[6];
    const float* ln2_g      = (const float*)d_in[7];
    const float* ln2_b      = (const float*)d_in[8];
    const float* router_w   = (const float*)d_in[9];
    const float* router_b   = (const float*)d_in[10];
    const float* w1         = (const float*)d_in[11];
    const float* b1         = (const float*)d_in[12];
    const float* w2         = (const float*)d_in[13];
    const float* b2         = (const float*)d_in[14];
    float* out = (float*)d_out;

    float *p_x2, *p_qkv, *p_scores, *p_ao, *p_xm, *p_xmr, *p_h, *p_y;
    cudaGetSymbolAddress((void**)&p_x2,     g_x2);
    cudaGetSymbolAddress((void**)&p_qkv,    g_qkv);
    cudaGetSymbolAddress((void**)&p_scores, g_scores);
    cudaGetSymbolAddress((void**)&p_ao,     g_ao);
    cudaGetSymbolAddress((void**)&p_xm,     g_xm);
    cudaGetSymbolAddress((void**)&p_xmr,    g_xmr);
    cudaGetSymbolAddress((void**)&p_h,      g_h);
    cudaGetSymbolAddress((void**)&p_y,      g_y);
    float *p_qw, *p_ow, *p_w1t, *p_w2t;
    cudaGetSymbolAddress((void**)&p_qw,  g_qkvw);
    cudaGetSymbolAddress((void**)&p_ow,  g_ow);
    cudaGetSymbolAddress((void**)&p_w1t, g_w1t);
    cudaGetSymbolAddress((void**)&p_w2t, g_w2t);

    cudaFuncSetAttribute(ca_gemm<false, false, 0>, cudaFuncAttributeMaxDynamicSharedMemorySize, CA_SMEM);
    cudaFuncSetAttribute(ca_gemm<false, false, 1>, cudaFuncAttributeMaxDynamicSharedMemorySize, CA_SMEM);
    cudaFuncSetAttribute(ca_gemm<true,  true,  2>, cudaFuncAttributeMaxDynamicSharedMemorySize, CA_SMEM);
    cudaFuncSetAttribute(ca_gemm<true,  false, 0>, cudaFuncAttributeMaxDynamicSharedMemorySize, CA_SMEM);

    // 0. weight preprocessing (round to tf32; transpose MoE weights to [N,K])
    round_kernel<<<(NQKV*D_ + 255)/256, 256>>>(in_proj_w, p_qw, NQKV*D_);
    round_kernel<<<(D_*D_ + 255)/256, 256>>>(out_proj_w, p_ow, D_*D_);
    tround_kernel<<<dim3(DFF/32, D_/32, E_), dim3(32, 8)>>>(w1, p_w1t, D_, DFF);
    tround_kernel<<<dim3(D_/32, DFF/32, E_), dim3(32, 8)>>>(w2, p_w2t, DFF, D_);

    // 1. LN1 (rounded out; feeds only QKV GEMM)
    ln_kernel<false><<<T_, 256>>>(x, ln1_g, ln1_b, p_x2, nullptr);

    // 2. QKV projection
    ca_gemm<false, false, 0><<<dim3(NQKV/256, T_/128), 256, CA_SMEM>>>(
        p_x2, D_, p_qw, 0, in_proj_b, 0, nullptr, p_qkv, NQKV, D_);

    // 3. scores = Q K^T / 8
    mma_gemm<128, true, 3, 1><<<dim3(S_/128, S_/128, B_*H_), 256>>>(
        p_qkv, NQKV, p_qkv, NQKV, p_scores, S_, DH, 0.125f);

    // 4. softmax
    softmax_kernel<<<B_*H_*S_, 128>>>(p_scores);

    // 5. context = P @ V (rounded output -> out-proj A)
    mma_gemm<64, false, 4, 2><<<dim3(1, S_/128, B_*H_), 256>>>(
        p_scores, S_, p_qkv, NQKV, p_ao, D_, S_, 1.f);

    // 6. out-proj + bias + residual
    ca_gemm<false, false, 1><<<dim3(D_/256, T_/128), 256, CA_SMEM>>>(
        p_ao, D_, p_ow, 0, out_proj_b, 0, x, out, D_, D_);

    // 7. LN2: FULL-precision xm (router) + rounded xmr (MoE GEMM1 A).
    //    Router must see full precision — top_k is discontinuous and flips
    //    expert choices on near-tie tokens if its input is pre-rounded.
    ln_kernel<true><<<T_, 256>>>(out, ln2_g, ln2_b, p_xm, p_xmr);

    // 8. routing (full-precision xm)
    moe_init_kernel<<<(MAX_ROWS + 255)/256, 256>>>();
    router_kernel<<<T_, 256>>>(p_xm, router_w, router_b);
    scan_kernel<<<1, 256>>>();
    assign_kernel<<<(T_ + 255)/256, 256>>>();

    // 9. MoE GEMM1: h = gelu(gather(xmr) @ w1t[e]^T + b1[e]), tf32-rounded
    ca_gemm<true, true, 2><<<dim3(DFF/256, MAX_TILES), 256, CA_SMEM>>>(
        p_xmr, D_, p_w1t, (long long)DFF*D_, b1, DFF, nullptr, p_h, DFF, D_);

    // 10. MoE GEMM2: y = h @ w2t[e]^T + b2[e]
    ca_gemm<true, false, 0><<<dim3(D_/256, MAX_TILES), 256, CA_SMEM>>>(
        p_h, DFF, p_w2t, (long long)D_*DFF, b2, D_, nullptr, p_y, D_, DFF);

    // 11. combine
    combine_kernel<<<(T_*D_)/256, 256>>>(out);
}

// round 11
// speedup vs baseline: 1.6603x; 1.6603x over previous
#include <cuda_runtime.h>
#include <cuda_fp16.h>
#include <math.h>
#include <stdint.h>

// ---------------- problem constants ----------------
#define B_   32
#define S_   512
#define D_   768
#define H_   12
#define DH   64
#define E_   8
#define DFF  3072
#define T_   (B_*S_)        // 16384 tokens
#define NQKV (3*D_)         // 2304

#define MAX_ROWS (2*T_ + E_*128)   // 33792 padded MoE assignment rows
#define MAX_TILES (MAX_ROWS/128)   // 264

// ---------------- device scratch (static globals; no allocs) ----------------
__device__ __align__(16) __half g_x2h[T_*D_];    // LN1 out (fp16, QKV A)
__device__ float g_qkv[T_*NQKV];                 // QKV out (fp32, attention reads)
__device__ float g_scores[B_*H_*S_*S_];
__device__ __align__(16) __half g_aoh[T_*D_];    // PV context (fp16, out-proj A)
__device__ float g_xm[T_*D_];                    // LN2 out FULL fp32 (router!)
__device__ __align__(16) __half g_xmrh[T_*D_];   // LN2 out fp16 (MoE1 A)
__device__ __align__(16) __half g_hh[MAX_ROWS*DFF]; // MoE hidden (fp16)
__device__ float g_y[MAX_ROWS*D_];
__device__ int   g_topi[T_*2];
__device__ float g_topw[T_*2];
__device__ int   g_cnt[E_];
__device__ int   g_off[E_+1];
__device__ int   g_cursor[E_];
__device__ int   g_rowidx[MAX_ROWS];
__device__ float g_rowwt[MAX_ROWS];
__device__ int   g_slot[T_*2];
__device__ int   g_tile_e[MAX_TILES];

// fp16 weights, K-major [N][K]
__device__ __align__(16) __half g_qkvw_h[NQKV*D_];
__device__ __align__(16) __half g_ow_h[D_*D_];
__device__ __align__(16) __half g_w1t_h[E_*DFF*D_];
__device__ __align__(16) __half g_w2t_h[E_*D_*DFF];

// ---------------- helpers ----------------
__device__ __forceinline__ unsigned f2tf32(float x) {
    unsigned u;
    asm("cvt.rna.tf32.f32 %0, %1;" : "=r"(u) : "f"(x));
    return u;
}
__device__ __forceinline__ float roundtf(float x) { return __uint_as_float(f2tf32(x)); }

__device__ __forceinline__ uint32_t smem_u32(const void* p) {
    uint32_t a;
    asm("{ .reg .u64 t; cvta.to.shared.u64 t, %1; cvt.u32.u64 %0, t; }" : "=r"(a) : "l"(p));
    return a;
}
__device__ __forceinline__ void mma_tf32(float c[4], const unsigned a[4], const unsigned b[2]) {
    asm volatile(
        "mma.sync.aligned.m16n8k8.row.col.f32.tf32.tf32.f32 "
        "{%0,%1,%2,%3}, {%4,%5,%6,%7}, {%8,%9}, {%0,%1,%2,%3};"
        : "+f"(c[0]), "+f"(c[1]), "+f"(c[2]), "+f"(c[3])
        : "r"(a[0]), "r"(a[1]), "r"(a[2]), "r"(a[3]), "r"(b[0]), "r"(b[1]));
}
__device__ __forceinline__ void mma_f16(float c[4], const uint32_t a[4], const uint32_t b[2]) {
    asm volatile(
        "mma.sync.aligned.m16n8k16.row.col.f32.f16.f16.f32 "
        "{%0,%1,%2,%3}, {%4,%5,%6,%7}, {%8,%9}, {%0,%1,%2,%3};"
        : "+f"(c[0]), "+f"(c[1]), "+f"(c[2]), "+f"(c[3])
        : "r"(a[0]), "r"(a[1]), "r"(a[2]), "r"(a[3]), "r"(b[0]), "r"(b[1]));
}
__device__ __forceinline__ void cp16(uint32_t dst, const void* src) {
    asm volatile("cp.async.cg.shared.global [%0], [%1], 16;" :: "r"(dst), "l"(src) : "memory");
}
__device__ __forceinline__ void cp16z(uint32_t dst, const void* src, int sz) {
    asm volatile("cp.async.cg.shared.global [%0], [%1], 16, %2;" :: "r"(dst), "l"(src), "r"(sz) : "memory");
}

// =====================================================================
// fp16 cp.async-pipelined GEMM: C[M,N] = A[M,K] @ B[N,K]^T, fp32 accum
// Tile 128x256, BK=32, 4 stages, 256 threads, warp tile 64x64.
// m16n8k16 f16 mma. SMEM rows: 40 halfs (80B) stride -> conflict-free
// (word index gid*20+tig (+4/+8/+12) mod 32 all distinct).
// Stage: A 128*80B = 10240B, B 256*80B = 20480B -> 30720B; 4 stages.
// EPI: 0 +bias | 1 +bias+resid | 2 +bias,GELU   OUTH: C stored as fp16
// =====================================================================
#define CA_STAGE_BYTES 30720
#define CA_SMEM (4*CA_STAGE_BYTES)   // 122880 bytes

template<bool MOE, bool GATHER, int EPI, bool OUTH>
__global__ void __launch_bounds__(256, 1) ca_gemm(
    const __half* __restrict__ A, int lda,
    const __half* __restrict__ Bw, long long bstride,
    const float* __restrict__ biasb, int biasstride,
    const float* __restrict__ resid, void* __restrict__ Cv, int ldc, int K)
{
    if (MOE) {
        int e = g_tile_e[blockIdx.y];
        if (e < 0) return;
        Bw    += (long long)e * bstride;
        biasb += (long long)e * biasstride;
    }
    extern __shared__ char smch[];
    uint32_t smb = smem_u32(smch);
    int tid = threadIdx.x, lane = tid & 31, wid = tid >> 5;
    int gid = lane >> 2, tig = lane & 3, wm = wid & 1, wn = wid >> 1;
    int m0 = blockIdx.y * 128, n0 = blockIdx.x * 256;

    // A loader: row am = tid>>1, two 16B chunks at (tid&1)*2 + {0,1}
    int am = tid >> 1, akq = (tid & 1) * 2;
    long long arow = GATHER ? (long long)g_rowidx[m0 + am] : (long long)(m0 + am);
    int asz = (GATHER && arow < 0) ? 0 : 16;
    const __half* abase = A + (arow < 0 ? 0 : arow) * (long long)lda + akq * 8;
    // B loader: row n0+tid, 4 chunks of 16B
    const __half* bbase = Bw + (long long)(n0 + tid) * K;
    uint32_t adst0 = smb + (uint32_t)(am * 80 + akq * 16);
    uint32_t bdst0 = smb + 10240u + (uint32_t)tid * 80u;

    int niter = K / 32;

    auto fill = [&](int c) {
        uint32_t so = (uint32_t)(c & 3) * CA_STAGE_BYTES;
        const __half* as = abase + c * 32;
        cp16z(adst0 + so,      as,     asz);
        cp16z(adst0 + so + 16, as + 8, asz);
        const __half* bs = bbase + c * 32;
#pragma unroll
        for (int q = 0; q < 4; q++) cp16(bdst0 + so + q * 16, bs + q * 8);
        asm volatile("cp.async.commit_group;" ::: "memory");
    };

    fill(0); fill(1); fill(2);

    float acc[4][8][4];
#pragma unroll
    for (int i = 0; i < 4; i++)
#pragma unroll
        for (int j = 0; j < 8; j++)
#pragma unroll
            for (int q = 0; q < 4; q++) acc[i][j][q] = 0.f;

    for (int c = 0; c < niter; c++) {
        asm volatile("cp.async.wait_group 2;" ::: "memory");
        __syncthreads();
        if (c + 3 < niter) {
            fill(c + 3);
        } else {
            asm volatile("cp.async.commit_group;" ::: "memory");  // keep invariant
        }

        const char* stg = smch + (size_t)(c & 3) * CA_STAGE_BYTES;

#pragma unroll
        for (int h = 0; h < 2; h++) {
            int hb = h * 32;
            uint32_t af[4][4], bf[8][2];
#pragma unroll
            for (int i = 0; i < 4; i++) {
                int r = wm * 64 + i * 16 + gid;
                const char* pa = stg + r * 80 + hb + tig * 4;
                af[i][0] = *(const uint32_t*)pa;
                af[i][1] = *(const uint32_t*)(pa + 8 * 80);
                af[i][2] = *(const uint32_t*)(pa + 16);
                af[i][3] = *(const uint32_t*)(pa + 8 * 80 + 16);
            }
#pragma unroll
            for (int j = 0; j < 8; j++) {
                int n = wn * 64 + j * 8 + gid;
                const char* pb = stg + 10240 + n * 80 + hb + tig * 4;
                bf[j][0] = *(const uint32_t*)pb;
                bf[j][1] = *(const uint32_t*)(pb + 16);
            }
#pragma unroll
            for (int i = 0; i < 4; i++)
#pragma unroll
                for (int j = 0; j < 8; j++)
                    mma_f16(acc[i][j], af[i], bf[j]);
        }
    }

    // epilogue
#pragma unroll
    for (int i = 0; i < 4; i++) {
        long long r0 = m0 + wm * 64 + i * 16 + gid;
        long long r1 = r0 + 8;
#pragma unroll
        for (int j = 0; j < 8; j++) {
            int cc = n0 + wn * 64 + j * 8 + 2 * tig;
            float b0 = biasb[cc], b1 = biasb[cc + 1];
            float v00 = acc[i][j][0] + b0, v01 = acc[i][j][1] + b1;
            float v10 = acc[i][j][2] + b0, v11 = acc[i][j][3] + b1;
            if (EPI == 1) {
                v00 += resid[r0 * ldc + cc]; v01 += resid[r0 * ldc + cc + 1];
                v10 += resid[r1 * ldc + cc]; v11 += resid[r1 * ldc + cc + 1];
            }
            if (EPI == 2) {
                v00 = 0.5f * v00 * (1.f + erff(v00 * 0.70710678118654752f));
                v01 = 0.5f * v01 * (1.f + erff(v01 * 0.70710678118654752f));
                v10 = 0.5f * v10 * (1.f + erff(v10 * 0.70710678118654752f));
                v11 = 0.5f * v11 * (1.f + erff(v11 * 0.70710678118654752f));
            }
            if (OUTH) {
                __half* Ch = (__half*)Cv;
                *(__half2*)&Ch[r0 * ldc + cc] = __floats2half2_rn(v00, v01);
                *(__half2*)&Ch[r1 * ldc + cc] = __floats2half2_rn(v10, v11);
            } else {
                float* Cf = (float*)Cv;
                Cf[r0 * ldc + cc]     = v00; Cf[r0 * ldc + cc + 1] = v01;
                Cf[r1 * ldc + cc]     = v10; Cf[r1 * ldc + cc + 1] = v11;
            }
        }
    }
}

// ---------------- weight preprocessing (convert to fp16) ----------------
__global__ void h_round_kernel(const float* __restrict__ w, __half* __restrict__ o, int n) {
    int i = blockIdx.x * 256 + threadIdx.x;
    if (i < n) o[i] = __float2half_rn(w[i]);
}
// transpose [e][R][C] fp32 -> [e][C][R] fp16
__global__ void h_tround_kernel(const float* __restrict__ w, __half* __restrict__ o, int R, int C) {
    __shared__ float t[32][33];
    int e = blockIdx.z;
    int r0 = blockIdx.y * 32, c0 = blockIdx.x * 32;
    const float* we = w + (size_t)e * R * C;
    int x = threadIdx.x, y = threadIdx.y;
#pragma unroll
    for (int i = 0; i < 32; i += 8)
        t[y + i][x] = we[(size_t)(r0 + y + i) * C + c0 + x];
    __syncthreads();
    size_t base = (size_t)e * R * C;
#pragma unroll
    for (int i = 0; i < 32; i += 8)
        o[base + (size_t)(c0 + y + i) * R + r0 + x] = __float2half_rn(t[x][y + i]);
}

// ---------------- LayerNorm ----------------
// DUAL=false: write fp16 out_h only.  DUAL=true: fp32 out_f (router) + fp16 out_h.
template<bool DUAL>
__global__ void ln_kernel(const float* __restrict__ x, const float* __restrict__ gam,
                          const float* __restrict__ bet, float* __restrict__ out_f,
                          __half* __restrict__ out_h) {
    int row = blockIdx.x;
    const float* xr = x + (size_t)row * D_;
    float v[3];
    float s = 0.f, s2 = 0.f;
#pragma unroll
    for (int i = 0; i < 3; i++) {
        v[i] = xr[threadIdx.x + i*256];
        s += v[i]; s2 += v[i]*v[i];
    }
    __shared__ float sh[16];
#pragma unroll
    for (int o = 16; o > 0; o >>= 1) {
        s  += __shfl_down_sync(0xffffffffu, s,  o);
        s2 += __shfl_down_sync(0xffffffffu, s2, o);
    }
    int w = threadIdx.x >> 5, l = threadIdx.x & 31;
    if (l == 0) { sh[w] = s; sh[w+8] = s2; }
    __syncthreads();
    if (threadIdx.x < 32) {
        float a  = (l < 8) ? sh[l]   : 0.f;
        float b2 = (l < 8) ? sh[l+8] : 0.f;
#pragma unroll
        for (int o = 4; o > 0; o >>= 1) {
            a  += __shfl_down_sync(0xffffffffu, a,  o);
            b2 += __shfl_down_sync(0xffffffffu, b2, o);
        }
        if (l == 0) { sh[0] = a; sh[1] = b2; }
    }
    __syncthreads();
    float mean = sh[0] * (1.f/D_);
    float var  = sh[1] * (1.f/D_) - mean*mean;
    float inv  = rsqrtf(var + 1e-5f);
#pragma unroll
    for (int i = 0; i < 3; i++) {
        int c = threadIdx.x + i*256;
        float r = (v[i] - mean) * inv * gam[c] + bet[c];
        if (DUAL) out_f[(size_t)row*D_ + c] = r;   // full precision for router
        out_h[(size_t)row*D_ + c] = __float2half_rn(r);
    }
}

// ---------------- mma.sync tf32 attention GEMMs ----------------
// EPI: 3 *scale | 4 plain.  OUTH: write fp16.  ATT: 1 scores, 2 AV
template<int BN, bool BNK, int EPI, int ATT, bool OUTH>
__global__ void __launch_bounds__(256) mma_gemm(
    const float* __restrict__ A, int lda,
    const float* __restrict__ Bb, int ldb,
    void* __restrict__ Cv, int ldc, int K, float scale)
{
    constexpr int WN  = BN / 4;
    constexpr int WNT = WN / 8;
    constexpr int LDA_S = 132;
    constexpr int LDB_S = BN + 4;

    __shared__ __align__(16) unsigned As[2][16][LDA_S];
    __shared__ __align__(16) unsigned Bs[2][16][LDB_S];

    int tid  = threadIdx.x;
    int lane = tid & 31, w = tid >> 5;
    int gid  = lane >> 2, tig = lane & 3;
    int wm   = w & 1, wn = w >> 1;
    int m0   = blockIdx.y * 128, n0 = blockIdx.x * BN;

    long long coff = 0;
    if (ATT == 1) {
        int z = blockIdx.z, b = z / H_, h = z % H_;
        A  += (size_t)(b * S_) * NQKV + h * DH;
        Bb += (size_t)(b * S_) * NQKV + D_ + h * DH;
        coff = (size_t)z * S_ * S_;
    }
    if (ATT == 2) {
        int z = blockIdx.z, b = z / H_, h = z % H_;
        A  += (size_t)z * S_ * S_;
        Bb += (size_t)(b * S_) * NQKV + 2 * D_ + h * DH;
        coff = (size_t)(b * S_) * D_ + h * DH;
    }

    int ar0 = tid >> 2, ak0 = (tid & 3) * 4;
    long long arow0 = m0 + ar0, arow1 = m0 + ar0 + 64;

    int bn0_t, bk0_t;
    if (BNK) { bn0_t = tid >> 2;        bk0_t = (tid & 3) * 4; }
    else     { bk0_t = tid / (BN / 4);  bn0_t = (tid % (BN / 4)) * 4; }
    constexpr int BCNT = BN / 64;

    float4 rA0, rA1, rB0, rB1;

    auto loadA = [&](int k0) {
        rA0 = *(const float4*)(A + arow0 * (long long)lda + k0 + ak0);
        rA1 = *(const float4*)(A + arow1 * (long long)lda + k0 + ak0);
    };
    auto stsA = [&](int buf) {
        As[buf][ak0+0][ar0] = f2tf32(rA0.x); As[buf][ak0+1][ar0] = f2tf32(rA0.y);
        As[buf][ak0+2][ar0] = f2tf32(rA0.z); As[buf][ak0+3][ar0] = f2tf32(rA0.w);
        As[buf][ak0+0][ar0+64] = f2tf32(rA1.x); As[buf][ak0+1][ar0+64] = f2tf32(rA1.y);
        As[buf][ak0+2][ar0+64] = f2tf32(rA1.z); As[buf][ak0+3][ar0+64] = f2tf32(rA1.w);
    };
    auto loadB = [&](int k0) {
        if (BNK) {
            rB0 = *(const float4*)(Bb + (long long)(n0 + bn0_t) * ldb + k0 + bk0_t);
            rB1 = *(const float4*)(Bb + (long long)(n0 + bn0_t + 64) * ldb + k0 + bk0_t);
        } else {
            rB0 = *(const float4*)(Bb + (long long)(k0 + bk0_t) * ldb + n0 + bn0_t);
            if (BCNT == 2)
                rB1 = *(const float4*)(Bb + (long long)(k0 + bk0_t + 8) * ldb + n0 + bn0_t);
        }
    };
    auto stsB = [&](int buf) {
        if (BNK) {
            Bs[buf][bk0_t+0][bn0_t] = f2tf32(rB0.x); Bs[buf][bk0_t+1][bn0_t] = f2tf32(rB0.y);
            Bs[buf][bk0_t+2][bn0_t] = f2tf32(rB0.z); Bs[buf][bk0_t+3][bn0_t] = f2tf32(rB0.w);
            Bs[buf][bk0_t+0][bn0_t+64] = f2tf32(rB1.x); Bs[buf][bk0_t+1][bn0_t+64] = f2tf32(rB1.y);
            Bs[buf][bk0_t+2][bn0_t+64] = f2tf32(rB1.z); Bs[buf][bk0_t+3][bn0_t+64] = f2tf32(rB1.w);
        } else {
            uint4 u0; u0.x = f2tf32(rB0.x); u0.y = f2tf32(rB0.y); u0.z = f2tf32(rB0.z); u0.w = f2tf32(rB0.w);
            *(uint4*)&Bs[buf][bk0_t][bn0_t] = u0;
            if (BCNT == 2) {
                uint4 u1; u1.x = f2tf32(rB1.x); u1.y = f2tf32(rB1.y); u1.z = f2tf32(rB1.z); u1.w = f2tf32(rB1.w);
                *(uint4*)&Bs[buf][bk0_t+8][bn0_t] = u1;
            }
        }
    };

    float acc[4][WNT][4];
#pragma unroll
    for (int i = 0; i < 4; i++)
#pragma unroll
        for (int j = 0; j < WNT; j++)
#pragma unroll
            for (int q = 0; q < 4; q++) acc[i][j][q] = 0.f;

    int niter = K / 16;
    loadA(0); loadB(0);
    stsA(0);  stsB(0);
    __syncthreads();

    for (int it = 0; it < niter; it++) {
        int buf = it & 1;
        if (it + 1 < niter) { loadA((it+1)*16); loadB((it+1)*16); }

#pragma unroll
        for (int ks = 0; ks < 16; ks += 8) {
            unsigned af[4][4];
#pragma unroll
            for (int i = 0; i < 4; i++) {
                int m = wm*64 + i*16 + gid;
                af[i][0] = As[buf][ks+tig  ][m];
                af[i][1] = As[buf][ks+tig  ][m+8];
                af[i][2] = As[buf][ks+tig+4][m];
                af[i][3] = As[buf][ks+tig+4][m+8];
            }
            unsigned bfg[WNT][2];
#pragma unroll
            for (int j = 0; j < WNT; j++) {
                int n = wn*WN + j*8 + gid;
                bfg[j][0] = Bs[buf][ks+tig  ][n];
                bfg[j][1] = Bs[buf][ks+tig+4][n];
            }
#pragma unroll
            for (int i = 0; i < 4; i++)
#pragma unroll
                for (int j = 0; j < WNT; j++)
                    mma_tf32(acc[i][j], af[i], bfg[j]);
        }

        if (it + 1 < niter) {
            stsA(buf ^ 1); stsB(buf ^ 1);
            __syncthreads();
        }
    }

#pragma unroll
    for (int i = 0; i < 4; i++) {
        long long r0 = m0 + wm*64 + i*16 + gid;
        long long r1 = r0 + 8;
#pragma unroll
        for (int j = 0; j < WNT; j++) {
            int c = n0 + wn*WN + j*8 + 2*tig;
            float v00 = acc[i][j][0], v01 = acc[i][j][1];
            float v10 = acc[i][j][2], v11 = acc[i][j][3];
            if (EPI == 3) { v00 *= scale; v01 *= scale; v10 *= scale; v11 *= scale; }
            if (OUTH) {
                __half* Ch = (__half*)Cv;
                *(__half2*)&Ch[coff + r0*ldc + c] = __floats2half2_rn(v00, v01);
                *(__half2*)&Ch[coff + r1*ldc + c] = __floats2half2_rn(v10, v11);
            } else {
                float* Cf = (float*)Cv;
                Cf[coff + r0*ldc + c]   = v00; Cf[coff + r0*ldc + c+1] = v01;
                Cf[coff + r1*ldc + c]   = v10; Cf[coff + r1*ldc + c+1] = v11;
            }
        }
    }
}

// ---------------- softmax over last axis (512), block per row ----------------
__global__ void softmax_kernel(float* __restrict__ scores)
{
    size_t row = blockIdx.x;
    float* p = scores + row * S_;
    int tid = threadIdx.x;  // 128
    float v[4];
    float m = -1e30f;
#pragma unroll
    for (int i = 0; i < 4; i++) { v[i] = p[tid + i*128]; m = fmaxf(m, v[i]); }
    __shared__ float sm[4];
#pragma unroll
    for (int o = 16; o > 0; o >>= 1) m = fmaxf(m, __shfl_xor_sync(0xffffffffu, m, o));
    if ((tid & 31) == 0) sm[tid >> 5] = m;
    __syncthreads();
    m = fmaxf(fmaxf(sm[0], sm[1]), fmaxf(sm[2], sm[3]));
    float s = 0.f;
#pragma unroll
    for (int i = 0; i < 4; i++) { v[i] = __expf(v[i] - m); s += v[i]; }
#pragma unroll
    for (int o = 16; o > 0; o >>= 1) s += __shfl_xor_sync(0xffffffffu, s, o);
    __shared__ float ss[4];
    if ((tid & 31) == 0) ss[tid >> 5] = s;
    __syncthreads();
    s = ss[0] + ss[1] + ss[2] + ss[3];
    float inv = 1.f / s;
#pragma unroll
    for (int i = 0; i < 4; i++) p[tid + i*128] = v[i] * inv;
}

// ---------------- MoE routing ----------------
__global__ void moe_init_kernel() {
    int i = blockIdx.x * blockDim.x + threadIdx.x;
    if (i < E_) g_cnt[i] = 0;
    if (i < MAX_ROWS) g_rowidx[i] = -1;
}

__global__ void router_kernel(const float* __restrict__ xm, const float* __restrict__ rw,
                              const float* __restrict__ rb)
{
    int t = blockIdx.x;
    int w = threadIdx.x >> 5, l = threadIdx.x & 31;
    const float* xr = xm + (size_t)t * D_;
    const float* wr = rw + (size_t)w * D_;
    float s = 0.f;
    for (int d = l; d < D_; d += 32) s += xr[d] * wr[d];
#pragma unroll
    for (int o = 16; o > 0; o >>= 1) s += __shfl_down_sync(0xffffffffu, s, o);
    __shared__ float sh[E_];
    if (l == 0) sh[w] = s + rb[w];
    __syncthreads();
    if (threadIdx.x == 0) {
        int e1 = 0; float l1 = sh[0];
        for (int e = 1; e < E_; e++) if (sh[e] > l1) { l1 = sh[e]; e1 = e; }
        int e2 = -1; float l2 = -1e30f;
        for (int e = 0; e < E_; e++) if (e != e1 && sh[e] > l2) { l2 = sh[e]; e2 = e; }
        float w1 = 1.f / (1.f + __expf(l2 - l1));
        g_topi[2*t] = e1; g_topi[2*t+1] = e2;
        g_topw[2*t] = w1; g_topw[2*t+1] = 1.f - w1;
        atomicAdd(&g_cnt[e1], 1);
        atomicAdd(&g_cnt[e2], 1);
    }
}

__global__ void scan_kernel() {
    if (threadIdx.x == 0) {
        int o = 0;
        for (int e = 0; e < E_; e++) {
            g_off[e] = o; g_cursor[e] = o;
            o += ((g_cnt[e] + 127) >> 7) << 7;
        }
        g_off[E_] = o;
    }
    __syncthreads();
    for (int t = threadIdx.x; t < MAX_TILES; t += blockDim.x) {
        int row = t << 7;
        int e = -1;
        for (int ee = 0; ee < E_; ee++)
            if (row >= g_off[ee] && row < g_off[ee+1]) e = ee;
        g_tile_e[t] = (row < g_off[E_]) ? e : -1;
    }
}

__global__ void assign_kernel() {
    int t = blockIdx.x * blockDim.x + threadIdx.x;
    if (t >= T_) return;
#pragma unroll
    for (int k = 0; k < 2; k++) {
        int e = g_topi[2*t + k];
        int pos = atomicAdd(&g_cursor[e], 1);
        g_rowidx[pos] = t;
        g_rowwt[pos]  = g_topw[2*t + k];
        g_slot[2*t + k] = pos;
    }
}

__global__ void combine_kernel(float* __restrict__ out) {
    int i = blockIdx.x * blockDim.x + threadIdx.x;
    int t = i / D_;
    int d = i - t * D_;
    int s0 = g_slot[2*t], s1 = g_slot[2*t + 1];
    out[i] += g_rowwt[s0] * g_y[(size_t)s0 * D_ + d]
            + g_rowwt[s1] * g_y[(size_t)s1 * D_ + d];
}

// ---------------- launch ----------------
extern "C" void kernel_launch(void* const* d_in, const int* in_sizes, int n_in,
                              void* d_out, int out_size)
{
    const float* x          = (const float*)d_in[0];
    const float* ln1_g      = (const float*)d_in[1];
    const float* ln1_b      = (const float*)d_in[2];
    const float* in_proj_w  = (const float*)d_in[3];
    const float* in_proj_b  = (const float*)d_in[4];
    const float* out_proj_w = (const float*)d_in[5];
    const float* out_proj_b = (const float*)d_in[6];
    const float* ln2_g      = (const float*)d_in[7];
    const float* ln2_b      = (const float*)d_in[8];
    const float* router_w   = (const float*)d_in[9];
    const float* router_b   = (const float*)d_in[10];
    const float* w1         = (const float*)d_in[11];
    const float* b1         = (const float*)d_in[12];
    const float* w2         = (const float*)d_in[13];
    const float* b2         = (const float*)d_in[14];
    float* out = (float*)d_out;

    float *p_qkv, *p_scores, *p_xm, *p_y;
    __half *p_x2h, *p_aoh, *p_xmrh, *p_hh;
    cudaGetSymbolAddress((void**)&p_x2h,    g_x2h);
    cudaGetSymbolAddress((void**)&p_qkv,    g_qkv);
    cudaGetSymbolAddress((void**)&p_scores, g_scores);
    cudaGetSymbolAddress((void**)&p_aoh,    g_aoh);
    cudaGetSymbolAddress((void**)&p_xm,     g_xm);
    cudaGetSymbolAddress((void**)&p_xmrh,   g_xmrh);
    cudaGetSymbolAddress((void**)&p_hh,     g_hh);
    cudaGetSymbolAddress((void**)&p_y,      g_y);
    __half *p_qw, *p_ow, *p_w1t, *p_w2t;
    cudaGetSymbolAddress((void**)&p_qw,  g_qkvw_h);
    cudaGetSymbolAddress((void**)&p_ow,  g_ow_h);
    cudaGetSymbolAddress((void**)&p_w1t, g_w1t_h);
    cudaGetSymbolAddress((void**)&p_w2t, g_w2t_h);

    cudaFuncSetAttribute(ca_gemm<false, false, 0, false>, cudaFuncAttributeMaxDynamicSharedMemorySize, CA_SMEM);
    cudaFuncSetAttribute(ca_gemm<false, false, 1, false>, cudaFuncAttributeMaxDynamicSharedMemorySize, CA_SMEM);
    cudaFuncSetAttribute(ca_gemm<true,  true,  2, true >, cudaFuncAttributeMaxDynamicSharedMemorySize, CA_SMEM);
    cudaFuncSetAttribute(ca_gemm<true,  false, 0, false>, cudaFuncAttributeMaxDynamicSharedMemorySize, CA_SMEM);

    // 0. weight preprocessing (fp16 convert; transpose MoE weights to [N,K])
    h_round_kernel<<<(NQKV*D_ + 255)/256, 256>>>(in_proj_w, p_qw, NQKV*D_);
    h_round_kernel<<<(D_*D_ + 255)/256, 256>>>(out_proj_w, p_ow, D_*D_);
    h_tround_kernel<<<dim3(DFF/32, D_/32, E_), dim3(32, 8)>>>(w1, p_w1t, D_, DFF);
    h_tround_kernel<<<dim3(D_/32, DFF/32, E_), dim3(32, 8)>>>(w2, p_w2t, DFF, D_);

    // 1. LN1 -> fp16
    ln_kernel<false><<<T_, 256>>>(x, ln1_g, ln1_b, nullptr, p_x2h);

    // 2. QKV projection (fp16 mma) -> fp32 qkv
    ca_gemm<false, false, 0, false><<<dim3(NQKV/256, T_/128), 256, CA_SMEM>>>(
        p_x2h, D_, p_qw, 0, in_proj_b, 0, nullptr, p_qkv, NQKV, D_);

    // 3. scores = Q K^T / 8 (tf32)
    mma_gemm<128, true, 3, 1, false><<<dim3(S_/128, S_/128, B_*H_), 256>>>(
        p_qkv, NQKV, p_qkv, NQKV, p_scores, S_, DH, 0.125f);

    // 4. softmax
    softmax_kernel<<<B_*H_*S_, 128>>>(p_scores);

    // 5. context = P @ V (tf32) -> fp16 ao
    mma_gemm<64, false, 4, 2, true><<<dim3(1, S_/128, B_*H_), 256>>>(
        p_scores, S_, p_qkv, NQKV, p_aoh, D_, S_, 1.f);

    // 6. out-proj + bias + residual (fp16 mma) -> fp32 out
    ca_gemm<false, false, 1, false><<<dim3(D_/256, T_/128), 256, CA_SMEM>>>(
        p_aoh, D_, p_ow, 0, out_proj_b, 0, x, out, D_, D_);

    // 7. LN2: FULL fp32 xm (router) + fp16 xmrh (MoE1 A)
    ln_kernel<true><<<T_, 256>>>(out, ln2_g, ln2_b, p_xm, p_xmrh);

    // 8. routing (full-precision xm)
    moe_init_kernel<<<(MAX_ROWS + 255)/256, 256>>>();
    router_kernel<<<T_, 256>>>(p_xm, router_w, router_b);
    scan_kernel<<<1, 256>>>();
    assign_kernel<<<(T_ + 255)/256, 256>>>();

    // 9. MoE GEMM1: h = gelu(gather(xmrh) @ w1t[e]^T + b1[e]) -> fp16 h
    ca_gemm<true, true, 2, true><<<dim3(DFF/256, MAX_TILES), 256, CA_SMEM>>>(
        p_xmrh, D_, p_w1t, (long long)DFF*D_, b1, DFF, nullptr, p_hh, DFF, D_);

    // 10. MoE GEMM2: y = h @ w2t[e]^T + b2[e] -> fp32 y
    ca_gemm<true, false, 0, false><<<dim3(D_/256, MAX_TILES), 256, CA_SMEM>>>(
        p_hh, DFF, p_w2t, (long long)D_*DFF, b2, D_, nullptr, p_y, D_, DFF);

    // 11. combine
    combine_kernel<<<(T_*D_)/256, 256>>>(out);
}

// round 16
// speedup vs baseline: 1.9908x; 1.1991x over previous
#include <cuda_runtime.h>
#include <cuda_fp16.h>
#include <math.h>
#include <stdint.h>

// ---------------- problem constants ----------------
#define B_   32
#define S_   512
#define D_   768
#define H_   12
#define DH   64
#define E_   8
#define DFF  3072
#define T_   (B_*S_)        // 16384 tokens
#define NQKV (3*D_)         // 2304

#define MAX_ROWS (2*T_ + E_*128)   // 33792 padded MoE assignment rows
#define MAX_TILES (MAX_ROWS/128)   // 264

// ---------------- device scratch (static globals; no allocs) ----------------
__device__ __align__(16) __half g_x2h[T_*D_];    // LN1 out (fp16, QKV A)
__device__ __align__(16) __half g_qkvh[T_*NQKV]; // QKV out (fp16, flash reads)
__device__ __align__(16) __half g_aoh[T_*D_];    // attention context (fp16, out-proj A)
__device__ float g_xm[T_*D_];                    // LN2 out FULL fp32 (router!)
__device__ __align__(16) __half g_xmrh[T_*D_];   // LN2 out fp16 (MoE1 A)
__device__ __align__(16) __half g_hh[MAX_ROWS*DFF]; // MoE hidden (fp16)
__device__ float g_y[MAX_ROWS*D_];
__device__ int   g_topi[T_*2];
__device__ float g_topw[T_*2];
__device__ int   g_cnt[E_];
__device__ int   g_off[E_+1];
__device__ int   g_cursor[E_];
__device__ int   g_rowidx[MAX_ROWS];
__device__ float g_rowwt[MAX_ROWS];
__device__ int   g_slot[T_*2];
__device__ int   g_tile_e[MAX_TILES];

// fp16 weights, K-major [N][K]
__device__ __align__(16) __half g_qkvw_h[NQKV*D_];
__device__ __align__(16) __half g_ow_h[D_*D_];
__device__ __align__(16) __half g_w1t_h[E_*DFF*D_];
__device__ __align__(16) __half g_w2t_h[E_*D_*DFF];

// ---------------- helpers ----------------
__device__ __forceinline__ uint32_t smem_u32(const void* p) {
    uint32_t a;
    asm("{ .reg .u64 t; cvta.to.shared.u64 t, %1; cvt.u32.u64 %0, t; }" : "=r"(a) : "l"(p));
    return a;
}
__device__ __forceinline__ void mma_f16(float c[4], const uint32_t a[4], const uint32_t b[2]) {
    asm volatile(
        "mma.sync.aligned.m16n8k16.row.col.f32.f16.f16.f32 "
        "{%0,%1,%2,%3}, {%4,%5,%6,%7}, {%8,%9}, {%0,%1,%2,%3};"
        : "+f"(c[0]), "+f"(c[1]), "+f"(c[2]), "+f"(c[3])
        : "r"(a[0]), "r"(a[1]), "r"(a[2]), "r"(a[3]), "r"(b[0]), "r"(b[1]));
}
__device__ __forceinline__ void cp16(uint32_t dst, const void* src) {
    asm volatile("cp.async.cg.shared.global [%0], [%1], 16;" :: "r"(dst), "l"(src) : "memory");
}
__device__ __forceinline__ void cp16z(uint32_t dst, const void* src, int sz) {
    asm volatile("cp.async.cg.shared.global [%0], [%1], 16, %2;" :: "r"(dst), "l"(src), "r"(sz) : "memory");
}
__device__ __forceinline__ uint32_t pack_h2(float a, float b) {
    __half2 h = __floats2half2_rn(a, b);
    return *(uint32_t*)&h;
}

// =====================================================================
// fp16 cp.async-pipelined GEMM: C[M,N] = A[M,K] @ B[N,K]^T, fp32 accum
// Tile 128x256, BK=32, 4 stages, 256 threads, warp tile 64x64.  (R9, passing)
// EPI: 0 +bias | 1 +bias+resid | 2 +bias,GELU   OUTH: C stored as fp16
// =====================================================================
#define CA_STAGE_BYTES 30720
#define CA_SMEM (4*CA_STAGE_BYTES)   // 122880 bytes

template<bool MOE, bool GATHER, int EPI, bool OUTH>
__global__ void __launch_bounds__(256, 1) ca_gemm(
    const __half* __restrict__ A, int lda,
    const __half* __restrict__ Bw, long long bstride,
    const float* __restrict__ biasb, int biasstride,
    const float* __restrict__ resid, void* __restrict__ Cv, int ldc, int K)
{
    if (MOE) {
        int e = g_tile_e[blockIdx.y];
        if (e < 0) return;
        Bw    += (long long)e * bstride;
        biasb += (long long)e * biasstride;
    }
    extern __shared__ char smch[];
    uint32_t smb = smem_u32(smch);
    int tid = threadIdx.x, lane = tid & 31, wid = tid >> 5;
    int gid = lane >> 2, tig = lane & 3, wm = wid & 1, wn = wid >> 1;
    int m0 = blockIdx.y * 128, n0 = blockIdx.x * 256;

    int am = tid >> 1, akq = (tid & 1) * 2;
    long long arow = GATHER ? (long long)g_rowidx[m0 + am] : (long long)(m0 + am);
    int asz = (GATHER && arow < 0) ? 0 : 16;
    const __half* abase = A + (arow < 0 ? 0 : arow) * (long long)lda + akq * 8;
    const __half* bbase = Bw + (long long)(n0 + tid) * K;
    uint32_t adst0 = smb + (uint32_t)(am * 80 + akq * 16);
    uint32_t bdst0 = smb + 10240u + (uint32_t)tid * 80u;

    int niter = K / 32;

    auto fill = [&](int c) {
        uint32_t so = (uint32_t)(c & 3) * CA_STAGE_BYTES;
        const __half* as = abase + c * 32;
        cp16z(adst0 + so,      as,     asz);
        cp16z(adst0 + so + 16, as + 8, asz);
        const __half* bs = bbase + c * 32;
#pragma unroll
        for (int q = 0; q < 4; q++) cp16(bdst0 + so + q * 16, bs + q * 8);
        asm volatile("cp.async.commit_group;" ::: "memory");
    };

    fill(0); fill(1); fill(2);

    float acc[4][8][4];
#pragma unroll
    for (int i = 0; i < 4; i++)
#pragma unroll
        for (int j = 0; j < 8; j++)
#pragma unroll
            for (int q = 0; q < 4; q++) acc[i][j][q] = 0.f;

    for (int c = 0; c < niter; c++) {
        asm volatile("cp.async.wait_group 2;" ::: "memory");
        __syncthreads();
        if (c + 3 < niter) {
            fill(c + 3);
        } else {
            asm volatile("cp.async.commit_group;" ::: "memory");  // keep invariant
        }

        const char* stg = smch + (size_t)(c & 3) * CA_STAGE_BYTES;

#pragma unroll
        for (int h = 0; h < 2; h++) {
            int hb = h * 32;
            uint32_t af[4][4], bf[8][2];
#pragma unroll
            for (int i = 0; i < 4; i++) {
                int r = wm * 64 + i * 16 + gid;
                const char* pa = stg + r * 80 + hb + tig * 4;
                af[i][0] = *(const uint32_t*)pa;
                af[i][1] = *(const uint32_t*)(pa + 8 * 80);
                af[i][2] = *(const uint32_t*)(pa + 16);
                af[i][3] = *(const uint32_t*)(pa + 8 * 80 + 16);
            }
#pragma unroll
            for (int j = 0; j < 8; j++) {
                int n = wn * 64 + j * 8 + gid;
                const char* pb = stg + 10240 + n * 80 + hb + tig * 4;
                bf[j][0] = *(const uint32_t*)pb;
                bf[j][1] = *(const uint32_t*)(pb + 16);
            }
#pragma unroll
            for (int i = 0; i < 4; i++)
#pragma unroll
                for (int j = 0; j < 8; j++)
                    mma_f16(acc[i][j], af[i], bf[j]);
        }
    }

#pragma unroll
    for (int i = 0; i < 4; i++) {
        long long r0 = m0 + wm * 64 + i * 16 + gid;
        long long r1 = r0 + 8;
#pragma unroll
        for (int j = 0; j < 8; j++) {
            int cc = n0 + wn * 64 + j * 8 + 2 * tig;
            float b0 = biasb[cc], b1 = biasb[cc + 1];
            float v00 = acc[i][j][0] + b0, v01 = acc[i][j][1] + b1;
            float v10 = acc[i][j][2] + b0, v11 = acc[i][j][3] + b1;
            if (EPI == 1) {
                v00 += resid[r0 * ldc + cc]; v01 += resid[r0 * ldc + cc + 1];
                v10 += resid[r1 * ldc + cc]; v11 += resid[r1 * ldc + cc + 1];
            }
            if (EPI == 2) {
                v00 = 0.5f * v00 * (1.f + erff(v00 * 0.70710678118654752f));
                v01 = 0.5f * v01 * (1.f + erff(v01 * 0.70710678118654752f));
                v10 = 0.5f * v10 * (1.f + erff(v10 * 0.70710678118654752f));
                v11 = 0.5f * v11 * (1.f + erff(v11 * 0.70710678118654752f));
            }
            if (OUTH) {
                __half* Ch = (__half*)Cv;
                *(__half2*)&Ch[r0 * ldc + cc] = __floats2half2_rn(v00, v01);
                *(__half2*)&Ch[r1 * ldc + cc] = __floats2half2_rn(v10, v11);
            } else {
                float* Cf = (float*)Cv;
                Cf[r0 * ldc + cc]     = v00; Cf[r0 * ldc + cc + 1] = v01;
                Cf[r1 * ldc + cc]     = v10; Cf[r1 * ldc + cc + 1] = v11;
            }
        }
    }
}

// =====================================================================
// Fused fp16 flash attention.
// Grid (4 q-tiles, B*H). 256 threads, 8 warps; warp owns 16 Q rows.
// Q tile 128x64 smem; KV tiles 64x64, triple-buffered cp.async.
// Row stride 144B (conflict-free for LDS.32 frags and ldmatrix.trans).
// =====================================================================
#define FL_SMEM (18432 + 3*9216 + 3*9216)   // 73728

__global__ void __launch_bounds__(256, 1) flash_kernel(
    const __half* __restrict__ qkv, __half* __restrict__ ao)
{
    extern __shared__ char sm[];
    int qt = blockIdx.x, z = blockIdx.y;
    int b = z / H_, h = z % H_;
    int tid = threadIdx.x, lane = tid & 31, wid = tid >> 5;
    int gid = lane >> 2, tig = lane & 3;
    uint32_t smb = smem_u32(sm);
    uint32_t Qb = smb, Kb0 = smb + 18432, Vb0 = smb + 18432 + 3*9216;

    const __half* qbase = qkv + (size_t)(b*S_ + qt*128)*NQKV + h*DH;
    const __half* kbase = qkv + (size_t)(b*S_)*NQKV + D_ + h*DH;
    const __half* vbase = qkv + (size_t)(b*S_)*NQKV + 2*D_ + h*DH;

    // Q load: 128 rows x 8 chunks of 16B
#pragma unroll
    for (int t = 0; t < 4; t++) {
        int idx = tid + t*256, r = idx >> 3, c = idx & 7;
        cp16(Qb + (uint32_t)(r*144 + c*16), qbase + (size_t)r*NQKV + c*8);
    }
    asm volatile("cp.async.commit_group;" ::: "memory");

    auto fillkv = [&](int kt) {
        uint32_t kb = Kb0 + (uint32_t)(kt % 3) * 9216u;
        uint32_t vb = Vb0 + (uint32_t)(kt % 3) * 9216u;
#pragma unroll
        for (int t = 0; t < 2; t++) {
            int idx = tid + t*256, r = idx >> 3, c = idx & 7;
            cp16(kb + (uint32_t)(r*144 + c*16), kbase + (size_t)(kt*64 + r)*NQKV + c*8);
            cp16(vb + (uint32_t)(r*144 + c*16), vbase + (size_t)(kt*64 + r)*NQKV + c*8);
        }
        asm volatile("cp.async.commit_group;" ::: "memory");
    };
    fillkv(0);

    float o[8][4];
#pragma unroll
    for (int nj = 0; nj < 8; nj++)
#pragma unroll
        for (int q = 0; q < 4; q++) o[nj][q] = 0.f;
    float m0 = -1e30f, m1 = -1e30f, l0 = 0.f, l1 = 0.f;
    int wq = wid * 16;

    for (int kt = 0; kt < 8; kt++) {
        if (kt + 1 < 8) fillkv(kt + 1);
        else asm volatile("cp.async.commit_group;" ::: "memory");
        asm volatile("cp.async.wait_group 1;" ::: "memory");
        __syncthreads();
        const char* kbp = sm + 18432 + (kt % 3) * 9216;
        uint32_t vb = Vb0 + (uint32_t)(kt % 3) * 9216u;

        // --- S = Q K^T ---
        float s[8][4];
#pragma unroll
        for (int j = 0; j < 8; j++)
#pragma unroll
            for (int q = 0; q < 4; q++) s[j][q] = 0.f;
#pragma unroll
        for (int kc = 0; kc < 4; kc++) {
            uint32_t a[4];
            const char* qa = sm + (wq + gid)*144 + kc*32 + tig*4;
            a[0] = *(const uint32_t*)qa;
            a[1] = *(const uint32_t*)(qa + 8*144);
            a[2] = *(const uint32_t*)(qa + 16);
            a[3] = *(const uint32_t*)(qa + 8*144 + 16);
#pragma unroll
            for (int j = 0; j < 8; j++) {
                const char* bp = kbp + (j*8 + gid)*144 + kc*32 + tig*4;
                uint32_t bf[2] = { *(const uint32_t*)bp, *(const uint32_t*)(bp + 16) };
                mma_f16(s[j], a, bf);
            }
        }
        // --- online softmax (fp32) ---
        float mt0 = -1e30f, mt1 = -1e30f;
#pragma unroll
        for (int j = 0; j < 8; j++) {
            s[j][0] *= 0.125f; s[j][1] *= 0.125f; s[j][2] *= 0.125f; s[j][3] *= 0.125f;
            mt0 = fmaxf(mt0, fmaxf(s[j][0], s[j][1]));
            mt1 = fmaxf(mt1, fmaxf(s[j][2], s[j][3]));
        }
        mt0 = fmaxf(mt0, __shfl_xor_sync(0xffffffffu, mt0, 1));
        mt0 = fmaxf(mt0, __shfl_xor_sync(0xffffffffu, mt0, 2));
        mt1 = fmaxf(mt1, __shfl_xor_sync(0xffffffffu, mt1, 1));
        mt1 = fmaxf(mt1, __shfl_xor_sync(0xffffffffu, mt1, 2));
        float mn0 = fmaxf(m0, mt0), mn1 = fmaxf(m1, mt1);
        float al0 = __expf(m0 - mn0), al1 = __expf(m1 - mn1);
        float r0 = 0.f, r1 = 0.f;
#pragma unroll
        for (int j = 0; j < 8; j++) {
            s[j][0] = __expf(s[j][0] - mn0); s[j][1] = __expf(s[j][1] - mn0);
            s[j][2] = __expf(s[j][2] - mn1); s[j][3] = __expf(s[j][3] - mn1);
            r0 += s[j][0] + s[j][1];
            r1 += s[j][2] + s[j][3];
        }
        r0 += __shfl_xor_sync(0xffffffffu, r0, 1); r0 += __shfl_xor_sync(0xffffffffu, r0, 2);
        r1 += __shfl_xor_sync(0xffffffffu, r1, 1); r1 += __shfl_xor_sync(0xffffffffu, r1, 2);
        l0 = l0 * al0 + r0; l1 = l1 * al1 + r1;
        m0 = mn0; m1 = mn1;
#pragma unroll
        for (int nj = 0; nj < 8; nj++) {
            o[nj][0] *= al0; o[nj][1] *= al0; o[nj][2] *= al1; o[nj][3] *= al1;
        }
        // --- P (C-frag) -> A-frag repack ---
        uint32_t ap[4][4];
#pragma unroll
        for (int kc = 0; kc < 4; kc++) {
            ap[kc][0] = pack_h2(s[2*kc][0],   s[2*kc][1]);
            ap[kc][1] = pack_h2(s[2*kc][2],   s[2*kc][3]);
            ap[kc][2] = pack_h2(s[2*kc+1][0], s[2*kc+1][1]);
            ap[kc][3] = pack_h2(s[2*kc+1][2], s[2*kc+1][3]);
        }
        // --- O += P @ V (V via ldmatrix.trans) ---
#pragma unroll
        for (int nj = 0; nj < 8; nj++) {
#pragma unroll
            for (int kc = 0; kc < 4; kc++) {
                uint32_t addr = vb + (uint32_t)((kc*16 + (lane & 15))*144 + nj*16);
                uint32_t bv0, bv1;
                asm volatile("ldmatrix.sync.aligned.m8n8.x2.trans.shared.b16 {%0,%1}, [%2];"
                             : "=r"(bv0), "=r"(bv1) : "r"(addr));
                uint32_t bv[2] = { bv0, bv1 };
                mma_f16(o[nj], ap[kc], bv);
            }
        }
    }

    // epilogue: out = O / l, fp16
    float il0 = 1.f / l0, il1 = 1.f / l1;
    size_t row0 = (size_t)(b*S_ + qt*128 + wq + gid);
#pragma unroll
    for (int nj = 0; nj < 8; nj++) {
        int col = h*DH + nj*8 + 2*tig;
        *(__half2*)&ao[row0*D_ + col]     = __floats2half2_rn(o[nj][0]*il0, o[nj][1]*il0);
        *(__half2*)&ao[(row0+8)*D_ + col] = __floats2half2_rn(o[nj][2]*il1, o[nj][3]*il1);
    }
}

// ---------------- weight preprocessing (convert to fp16) ----------------
__global__ void h_round_kernel(const float* __restrict__ w, __half* __restrict__ o, int n) {
    int i = blockIdx.x * 256 + threadIdx.x;
    if (i < n) o[i] = __float2half_rn(w[i]);
}
__global__ void h_tround_kernel(const float* __restrict__ w, __half* __restrict__ o, int R, int C) {
    __shared__ float t[32][33];
    int e = blockIdx.z;
    int r0 = blockIdx.y * 32, c0 = blockIdx.x * 32;
    const float* we = w + (size_t)e * R * C;
    int x = threadIdx.x, y = threadIdx.y;
#pragma unroll
    for (int i = 0; i < 32; i += 8)
        t[y + i][x] = we[(size_t)(r0 + y + i) * C + c0 + x];
    __syncthreads();
    size_t base = (size_t)e * R * C;
#pragma unroll
    for (int i = 0; i < 32; i += 8)
        o[base + (size_t)(c0 + y + i) * R + r0 + x] = __float2half_rn(t[x][y + i]);
}

// ---------------- LayerNorm ----------------
template<bool DUAL>
__global__ void ln_kernel(const float* __restrict__ x, const float* __restrict__ gam,
                          const float* __restrict__ bet, float* __restrict__ out_f,
                          __half* __restrict__ out_h) {
    int row = blockIdx.x;
    const float* xr = x + (size_t)row * D_;
    float v[3];
    float s = 0.f, s2 = 0.f;
#pragma unroll
    for (int i = 0; i < 3; i++) {
        v[i] = xr[threadIdx.x + i*256];
        s += v[i]; s2 += v[i]*v[i];
    }
    __shared__ float sh[16];
#pragma unroll
    for (int o = 16; o > 0; o >>= 1) {
        s  += __shfl_down_sync(0xffffffffu, s,  o);
        s2 += __shfl_down_sync(0xffffffffu, s2, o);
    }
    int w = threadIdx.x >> 5, l = threadIdx.x & 31;
    if (l == 0) { sh[w] = s; sh[w+8] = s2; }
    __syncthreads();
    if (threadIdx.x < 32) {
        float a  = (l < 8) ? sh[l]   : 0.f;
        float b2 = (l < 8) ? sh[l+8] : 0.f;
#pragma unroll
        for (int o = 4; o > 0; o >>= 1) {
            a  += __shfl_down_sync(0xffffffffu, a,  o);
            b2 += __shfl_down_sync(0xffffffffu, b2, o);
        }
        if (l == 0) { sh[0] = a; sh[1] = b2; }
    }
    __syncthreads();
    float mean = sh[0] * (1.f/D_);
    float var  = sh[1] * (1.f/D_) - mean*mean;
    float inv  = rsqrtf(var + 1e-5f);
#pragma unroll
    for (int i = 0; i < 3; i++) {
        int c = threadIdx.x + i*256;
        float r = (v[i] - mean) * inv * gam[c] + bet[c];
        if (DUAL) out_f[(size_t)row*D_ + c] = r;   // full precision for router
        out_h[(size_t)row*D_ + c] = __float2half_rn(r);
    }
}

// ---------------- MoE routing ----------------
__global__ void moe_init_kernel() {
    int i = blockIdx.x * blockDim.x + threadIdx.x;
    if (i < E_) g_cnt[i] = 0;
    if (i < MAX_ROWS) g_rowidx[i] = -1;
}

__global__ void router_kernel(const float* __restrict__ xm, const float* __restrict__ rw,
                              const float* __restrict__ rb)
{
    int t = blockIdx.x;
    int w = threadIdx.x >> 5, l = threadIdx.x & 31;
    const float* xr = xm + (size_t)t * D_;
    const float* wr = rw + (size_t)w * D_;
    float s = 0.f;
    for (int d = l; d < D_; d += 32) s += xr[d] * wr[d];
#pragma unroll
    for (int o = 16; o > 0; o >>= 1) s += __shfl_down_sync(0xffffffffu, s, o);
    __shared__ float sh[E_];
    if (l == 0) sh[w] = s + rb[w];
    __syncthreads();
    if (threadIdx.x == 0) {
        int e1 = 0; float l1 = sh[0];
        for (int e = 1; e < E_; e++) if (sh[e] > l1) { l1 = sh[e]; e1 = e; }
        int e2 = -1; float l2 = -1e30f;
        for (int e = 0; e < E_; e++) if (e != e1 && sh[e] > l2) { l2 = sh[e]; e2 = e; }
        float w1 = 1.f / (1.f + __expf(l2 - l1));
        g_topi[2*t] = e1; g_topi[2*t+1] = e2;
        g_topw[2*t] = w1; g_topw[2*t+1] = 1.f - w1;
        atomicAdd(&g_cnt[e1], 1);
        atomicAdd(&g_cnt[e2], 1);
    }
}

__global__ void scan_kernel() {
    if (threadIdx.x == 0) {
        int o = 0;
        for (int e = 0; e < E_; e++) {
            g_off[e] = o; g_cursor[e] = o;
            o += ((g_cnt[e] + 127) >> 7) << 7;
        }
        g_off[E_] = o;
    }
    __syncthreads();
    for (int t = threadIdx.x; t < MAX_TILES; t += blockDim.x) {
        int row = t << 7;
        int e = -1;
        for (int ee = 0; ee < E_; ee++)
            if (row >= g_off[ee] && row < g_off[ee+1]) e = ee;
        g_tile_e[t] = (row < g_off[E_]) ? e : -1;
    }
}

__global__ void assign_kernel() {
    int t = blockIdx.x * blockDim.x + threadIdx.x;
    if (t >= T_) return;
#pragma unroll
    for (int k = 0; k < 2; k++) {
        int e = g_topi[2*t + k];
        int pos = atomicAdd(&g_cursor[e], 1);
        g_rowidx[pos] = t;
        g_rowwt[pos]  = g_topw[2*t + k];
        g_slot[2*t + k] = pos;
    }
}

__global__ void combine_kernel(float* __restrict__ out) {
    int i = blockIdx.x * blockDim.x + threadIdx.x;
    int t = i / D_;
    int d = i - t * D_;
    int s0 = g_slot[2*t], s1 = g_slot[2*t + 1];
    out[i] += g_rowwt[s0] * g_y[(size_t)s0 * D_ + d]
            + g_rowwt[s1] * g_y[(size_t)s1 * D_ + d];
}

// ---------------- launch ----------------
extern "C" void kernel_launch(void* const* d_in, const int* in_sizes, int n_in,
                              void* d_out, int out_size)
{
    const float* x          = (const float*)d_in[0];
    const float* ln1_g      = (const float*)d_in[1];
    const float* ln1_b      = (const float*)d_in[2];
    const float* in_proj_w  = (const float*)d_in[3];
    const float* in_proj_b  = (const float*)d_in[4];
    const float* out_proj_w = (const float*)d_in[5];
    const float* out_proj_b = (const float*)d_in[6];
    const float* ln2_g      = (const float*)d_in[7];
    const float* ln2_b      = (const float*)d_in[8];
    const float* router_w   = (const float*)d_in[9];
    const float* router_b   = (const float*)d_in[10];
    const float* w1         = (const float*)d_in[11];
    const float* b1         = (const float*)d_in[12];
    const float* w2         = (const float*)d_in[13];
    const float* b2         = (const float*)d_in[14];
    float* out = (float*)d_out;

    float *p_xm, *p_y;
    __half *p_x2h, *p_qkvh, *p_aoh, *p_xmrh, *p_hh;
    cudaGetSymbolAddress((void**)&p_x2h,    g_x2h);
    cudaGetSymbolAddress((void**)&p_qkvh,   g_qkvh);
    cudaGetSymbolAddress((void**)&p_aoh,    g_aoh);
    cudaGetSymbolAddress((void**)&p_xm,     g_xm);
    cudaGetSymbolAddress((void**)&p_xmrh,   g_xmrh);
    cudaGetSymbolAddress((void**)&p_hh,     g_hh);
    cudaGetSymbolAddress((void**)&p_y,      g_y);
    __half *p_qw, *p_ow, *p_w1t, *p_w2t;
    cudaGetSymbolAddress((void**)&p_qw,  g_qkvw_h);
    cudaGetSymbolAddress((void**)&p_ow,  g_ow_h);
    cudaGetSymbolAddress((void**)&p_w1t, g_w1t_h);
    cudaGetSymbolAddress((void**)&p_w2t, g_w2t_h);

    cudaFuncSetAttribute(ca_gemm<false, false, 0, true >, cudaFuncAttributeMaxDynamicSharedMemorySize, CA_SMEM);
    cudaFuncSetAttribute(ca_gemm<false, false, 1, false>, cudaFuncAttributeMaxDynamicSharedMemorySize, CA_SMEM);
    cudaFuncSetAttribute(ca_gemm<true,  true,  2, true >, cudaFuncAttributeMaxDynamicSharedMemorySize, CA_SMEM);
    cudaFuncSetAttribute(ca_gemm<true,  false, 0, false>, cudaFuncAttributeMaxDynamicSharedMemorySize, CA_SMEM);
    cudaFuncSetAttribute(flash_kernel, cudaFuncAttributeMaxDynamicSharedMemorySize, FL_SMEM);

    // 0. weight preprocessing (fp16 convert; transpose MoE weights to [N,K])
    h_round_kernel<<<(NQKV*D_ + 255)/256, 256>>>(in_proj_w, p_qw, NQKV*D_);
    h_round_kernel<<<(D_*D_ + 255)/256, 256>>>(out_proj_w, p_ow, D_*D_);
    h_tround_kernel<<<dim3(DFF/32, D_/32, E_), dim3(32, 8)>>>(w1, p_w1t, D_, DFF);
    h_tround_kernel<<<dim3(D_/32, DFF/32, E_), dim3(32, 8)>>>(w2, p_w2t, DFF, D_);

    // 1. LN1 -> fp16
    ln_kernel<false><<<T_, 256>>>(x, ln1_g, ln1_b, nullptr, p_x2h);

    // 2. QKV projection (fp16 mma) -> fp16 qkv
    ca_gemm<false, false, 0, true><<<dim3(NQKV/256, T_/128), 256, CA_SMEM>>>(
        p_x2h, D_, p_qw, 0, in_proj_b, 0, nullptr, p_qkvh, NQKV, D_);

    // 3-5. fused flash attention -> fp16 ao
    flash_kernel<<<dim3(S_/128, B_*H_), 256, FL_SMEM>>>(p_qkvh, p_aoh);

    // 6. out-proj + bias + residual (fp16 mma) -> fp32 out
    ca_gemm<false, false, 1, false><<<dim3(D_/256, T_/128), 256, CA_SMEM>>>(
        p_aoh, D_, p_ow, 0, out_proj_b, 0, x, out, D_, D_);

    // 7. LN2: FULL fp32 xm (router) + fp16 xmrh (MoE1 A)
    ln_kernel<true><<<T_, 256>>>(out, ln2_g, ln2_b, p_xm, p_xmrh);

    // 8. routing (full-precision xm)
    moe_init_kernel<<<(MAX_ROWS + 255)/256, 256>>>();
    router_kernel<<<T_, 256>>>(p_xm, router_w, router_b);
    scan_kernel<<<1, 256>>>();
    assign_kernel<<<(T_ + 255)/256, 256>>>();

    // 9. MoE GEMM1: h = gelu(gather(xmrh) @ w1t[e]^T + b1[e]) -> fp16 h
    ca_gemm<true, true, 2, true><<<dim3(DFF/256, MAX_TILES), 256, CA_SMEM>>>(
        p_xmrh, D_, p_w1t, (long long)DFF*D_, b1, DFF, nullptr, p_hh, DFF, D_);

    // 10. MoE GEMM2: y = h @ w2t[e]^T + b2[e] -> fp32 y
    ca_gemm<true, false, 0, false><<<dim3(D_/256, MAX_TILES), 256, CA_SMEM>>>(
        p_hh, DFF, p_w2t, (long long)D_*DFF, b2, D_, nullptr, p_y, D_, DFF);

    // 11. combine
    combine_kernel<<<(T_*D_)/256, 256>>>(out);
}

// round 17
// speedup vs baseline: 2.0488x; 1.0291x over previous
#include <cuda_runtime.h>
#include <cuda_fp16.h>
#include <math.h>
#include <stdint.h>

// ---------------- problem constants ----------------
#define B_   32
#define S_   512
#define D_   768
#define H_   12
#define DH   64
#define E_   8
#define DFF  3072
#define T_   (B_*S_)        // 16384 tokens
#define NQKV (3*D_)         // 2304

#define MAX_ROWS (2*T_ + E_*128)   // 33792 padded MoE assignment rows
#define MAX_TILES (MAX_ROWS/128)   // 264

// ---------------- device scratch (static globals; no allocs) ----------------
__device__ __align__(16) __half g_x2h[T_*D_];    // LN1 out (fp16, QKV A)
__device__ __align__(16) __half g_qkvh[T_*NQKV]; // QKV out (fp16, flash reads)
__device__ __align__(16) __half g_aoh[T_*D_];    // attention context (fp16, out-proj A)
__device__ float g_xm[T_*D_];                    // LN2 out FULL fp32 (router!)
__device__ __align__(16) __half g_xmrh[T_*D_];   // LN2 out fp16 (MoE1 A)
__device__ __align__(16) __half g_hh[MAX_ROWS*DFF]; // MoE hidden (fp16)
__device__ float g_y[MAX_ROWS*D_];
__device__ int   g_topi[T_*2];
__device__ float g_topw[T_*2];
__device__ int   g_cnt[E_];
__device__ int   g_off[E_+1];
__device__ int   g_cursor[E_];
__device__ int   g_rowidx[MAX_ROWS];
__device__ float g_rowwt[MAX_ROWS];
__device__ int   g_slot[T_*2];
__device__ int   g_tile_e[MAX_TILES];

// fp16 weights, K-major [N][K]
__device__ __align__(16) __half g_qkvw_h[NQKV*D_];
__device__ __align__(16) __half g_ow_h[D_*D_];
__device__ __align__(16) __half g_w1t_h[E_*DFF*D_];
__device__ __align__(16) __half g_w2t_h[E_*D_*DFF];

// ---------------- helpers ----------------
__device__ __forceinline__ uint32_t smem_u32(const void* p) {
    uint32_t a;
    asm("{ .reg .u64 t; cvta.to.shared.u64 t, %1; cvt.u32.u64 %0, t; }" : "=r"(a) : "l"(p));
    return a;
}
__device__ __forceinline__ void mma_f16(float c[4], const uint32_t a[4], const uint32_t b[2]) {
    asm volatile(
        "mma.sync.aligned.m16n8k16.row.col.f32.f16.f16.f32 "
        "{%0,%1,%2,%3}, {%4,%5,%6,%7}, {%8,%9}, {%0,%1,%2,%3};"
        : "+f"(c[0]), "+f"(c[1]), "+f"(c[2]), "+f"(c[3])
        : "r"(a[0]), "r"(a[1]), "r"(a[2]), "r"(a[3]), "r"(b[0]), "r"(b[1]));
}
__device__ __forceinline__ void ldm_x4(uint32_t r[4], uint32_t addr) {
    asm volatile("ldmatrix.sync.aligned.m8n8.x4.shared.b16 {%0,%1,%2,%3}, [%4];"
                 : "=r"(r[0]), "=r"(r[1]), "=r"(r[2]), "=r"(r[3]) : "r"(addr));
}
__device__ __forceinline__ void cp16(uint32_t dst, const void* src) {
    asm volatile("cp.async.cg.shared.global [%0], [%1], 16;" :: "r"(dst), "l"(src) : "memory");
}
__device__ __forceinline__ void cp16z(uint32_t dst, const void* src, int sz) {
    asm volatile("cp.async.cg.shared.global [%0], [%1], 16, %2;" :: "r"(dst), "l"(src), "r"(sz) : "memory");
}
__device__ __forceinline__ uint32_t pack_h2(float a, float b) {
    __half2 h = __floats2half2_rn(a, b);
    return *(uint32_t*)&h;
}

// =====================================================================
// fp16 cp.async-pipelined GEMM: C[M,N] = A[M,K] @ B[N,K]^T, fp32 accum
// Tile 128x256, BK=32, 4 stages, 256 threads, warp tile 64x64.
// Fragments via ldmatrix.x4 (A: 4/half, B: 4/half covering 2 n-tiles each).
// 80B row stride: ldmatrix 8-row phases hit word offsets {0,20,8,28,16,4,24,12}
// mod 32 -> conflict-free.
// EPI: 0 +bias | 1 +bias+resid | 2 +bias,GELU   OUTH: C stored as fp16
// =====================================================================
#define CA_STAGE_BYTES 30720
#define CA_SMEM (4*CA_STAGE_BYTES)   // 122880 bytes

template<bool MOE, bool GATHER, int EPI, bool OUTH>
__global__ void __launch_bounds__(256, 1) ca_gemm(
    const __half* __restrict__ A, int lda,
    const __half* __restrict__ Bw, long long bstride,
    const float* __restrict__ biasb, int biasstride,
    const float* __restrict__ resid, void* __restrict__ Cv, int ldc, int K)
{
    if (MOE) {
        int e = g_tile_e[blockIdx.y];
        if (e < 0) return;
        Bw    += (long long)e * bstride;
        biasb += (long long)e * biasstride;
    }
    extern __shared__ char smch[];
    uint32_t smb = smem_u32(smch);
    int tid = threadIdx.x, lane = tid & 31, wid = tid >> 5;
    int gid = lane >> 2, tig = lane & 3, wm = wid & 1, wn = wid >> 1;
    int m0 = blockIdx.y * 128, n0 = blockIdx.x * 256;

    int am = tid >> 1, akq = (tid & 1) * 2;
    long long arow = GATHER ? (long long)g_rowidx[m0 + am] : (long long)(m0 + am);
    int asz = (GATHER && arow < 0) ? 0 : 16;
    const __half* abase = A + (arow < 0 ? 0 : arow) * (long long)lda + akq * 8;
    const __half* bbase = Bw + (long long)(n0 + tid) * K;
    uint32_t adst0 = smb + (uint32_t)(am * 80 + akq * 16);
    uint32_t bdst0 = smb + 10240u + (uint32_t)tid * 80u;

    int niter = K / 32;

    auto fill = [&](int c) {
        uint32_t so = (uint32_t)(c & 3) * CA_STAGE_BYTES;
        const __half* as = abase + c * 32;
        cp16z(adst0 + so,      as,     asz);
        cp16z(adst0 + so + 16, as + 8, asz);
        const __half* bs = bbase + c * 32;
#pragma unroll
        for (int q = 0; q < 4; q++) cp16(bdst0 + so + q * 16, bs + q * 8);
        asm volatile("cp.async.commit_group;" ::: "memory");
    };

    fill(0); fill(1); fill(2);

    float acc[4][8][4];
#pragma unroll
    for (int i = 0; i < 4; i++)
#pragma unroll
        for (int j = 0; j < 8; j++)
#pragma unroll
            for (int q = 0; q < 4; q++) acc[i][j][q] = 0.f;

    // ldmatrix address components (constant across chunks)
    int l15 = lane & 15, l16 = lane >> 4;       // A: row-within-16, k-chunk
    int bg  = lane >> 3, br = lane & 7;         // B: matrix group, row
    int bjo = (bg >> 1) * 8 + br;               // j-subtile row offset (j parity via bg>>1)
    int bko = (bg & 1) * 16;                    // k-chunk byte offset

    for (int c = 0; c < niter; c++) {
        asm volatile("cp.async.wait_group 2;" ::: "memory");
        __syncthreads();
        if (c + 3 < niter) {
            fill(c + 3);
        } else {
            asm volatile("cp.async.commit_group;" ::: "memory");  // keep invariant
        }

        uint32_t stgu = smb + (uint32_t)(c & 3) * CA_STAGE_BYTES;

#pragma unroll
        for (int h = 0; h < 2; h++) {
            int hb = h * 32;
            uint32_t af[4][4], bf[8][2];
#pragma unroll
            for (int i = 0; i < 4; i++) {
                uint32_t addr = stgu + (uint32_t)((wm*64 + i*16 + l15) * 80 + hb + l16*16);
                ldm_x4(af[i], addr);
            }
#pragma unroll
            for (int jp = 0; jp < 4; jp++) {
                uint32_t addr = stgu + 10240u +
                    (uint32_t)((wn*64 + jp*16 + bjo) * 80 + hb + bko);
                uint32_t r[4];
                ldm_x4(r, addr);
                bf[2*jp][0]   = r[0]; bf[2*jp][1]   = r[1];
                bf[2*jp+1][0] = r[2]; bf[2*jp+1][1] = r[3];
            }
#pragma unroll
            for (int i = 0; i < 4; i++)
#pragma unroll
                for (int j = 0; j < 8; j++)
                    mma_f16(acc[i][j], af[i], bf[j]);
        }
    }

    // epilogue
#pragma unroll
    for (int i = 0; i < 4; i++) {
        long long r0 = m0 + wm * 64 + i * 16 + gid;
        long long r1 = r0 + 8;
#pragma unroll
        for (int j = 0; j < 8; j++) {
            int cc = n0 + wn * 64 + j * 8 + 2 * tig;
            float b0 = biasb[cc], b1 = biasb[cc + 1];
            float v00 = acc[i][j][0] + b0, v01 = acc[i][j][1] + b1;
            float v10 = acc[i][j][2] + b0, v11 = acc[i][j][3] + b1;
            if (EPI == 1) {
                v00 += resid[r0 * ldc + cc]; v01 += resid[r0 * ldc + cc + 1];
                v10 += resid[r1 * ldc + cc]; v11 += resid[r1 * ldc + cc + 1];
            }
            if (EPI == 2) {
                v00 = 0.5f * v00 * (1.f + erff(v00 * 0.70710678118654752f));
                v01 = 0.5f * v01 * (1.f + erff(v01 * 0.70710678118654752f));
                v10 = 0.5f * v10 * (1.f + erff(v10 * 0.70710678118654752f));
                v11 = 0.5f * v11 * (1.f + erff(v11 * 0.70710678118654752f));
            }
            if (OUTH) {
                __half* Ch = (__half*)Cv;
                *(__half2*)&Ch[r0 * ldc + cc] = __floats2half2_rn(v00, v01);
                *(__half2*)&Ch[r1 * ldc + cc] = __floats2half2_rn(v10, v11);
            } else {
                float* Cf = (float*)Cv;
                Cf[r0 * ldc + cc]     = v00; Cf[r0 * ldc + cc + 1] = v01;
                Cf[r1 * ldc + cc]     = v10; Cf[r1 * ldc + cc + 1] = v11;
            }
        }
    }
}

// =====================================================================
// Fused fp16 flash attention (unchanged from R11, passing).
// =====================================================================
#define FL_SMEM (18432 + 3*9216 + 3*9216)   // 73728

__global__ void __launch_bounds__(256, 1) flash_kernel(
    const __half* __restrict__ qkv, __half* __restrict__ ao)
{
    extern __shared__ char sm[];
    int qt = blockIdx.x, z = blockIdx.y;
    int b = z / H_, h = z % H_;
    int tid = threadIdx.x, lane = tid & 31, wid = tid >> 5;
    int gid = lane >> 2, tig = lane & 3;
    uint32_t smb = smem_u32(sm);
    uint32_t Qb = smb, Kb0 = smb + 18432, Vb0 = smb + 18432 + 3*9216;

    const __half* qbase = qkv + (size_t)(b*S_ + qt*128)*NQKV + h*DH;
    const __half* kbase = qkv + (size_t)(b*S_)*NQKV + D_ + h*DH;
    const __half* vbase = qkv + (size_t)(b*S_)*NQKV + 2*D_ + h*DH;

#pragma unroll
    for (int t = 0; t < 4; t++) {
        int idx = tid + t*256, r = idx >> 3, c = idx & 7;
        cp16(Qb + (uint32_t)(r*144 + c*16), qbase + (size_t)r*NQKV + c*8);
    }
    asm volatile("cp.async.commit_group;" ::: "memory");

    auto fillkv = [&](int kt) {
        uint32_t kb = Kb0 + (uint32_t)(kt % 3) * 9216u;
        uint32_t vb = Vb0 + (uint32_t)(kt % 3) * 9216u;
#pragma unroll
        for (int t = 0; t < 2; t++) {
            int idx = tid + t*256, r = idx >> 3, c = idx & 7;
            cp16(kb + (uint32_t)(r*144 + c*16), kbase + (size_t)(kt*64 + r)*NQKV + c*8);
            cp16(vb + (uint32_t)(r*144 + c*16), vbase + (size_t)(kt*64 + r)*NQKV + c*8);
        }
        asm volatile("cp.async.commit_group;" ::: "memory");
    };
    fillkv(0);

    float o[8][4];
#pragma unroll
    for (int nj = 0; nj < 8; nj++)
#pragma unroll
        for (int q = 0; q < 4; q++) o[nj][q] = 0.f;
    float m0 = -1e30f, m1 = -1e30f, l0 = 0.f, l1 = 0.f;
    int wq = wid * 16;

    for (int kt = 0; kt < 8; kt++) {
        if (kt + 1 < 8) fillkv(kt + 1);
        else asm volatile("cp.async.commit_group;" ::: "memory");
        asm volatile("cp.async.wait_group 1;" ::: "memory");
        __syncthreads();
        const char* kbp = sm + 18432 + (kt % 3) * 9216;
        uint32_t vb = Vb0 + (uint32_t)(kt % 3) * 9216u;

        float s[8][4];
#pragma unroll
        for (int j = 0; j < 8; j++)
#pragma unroll
            for (int q = 0; q < 4; q++) s[j][q] = 0.f;
#pragma unroll
        for (int kc = 0; kc < 4; kc++) {
            uint32_t a[4];
            const char* qa = sm + (wq + gid)*144 + kc*32 + tig*4;
            a[0] = *(const uint32_t*)qa;
            a[1] = *(const uint32_t*)(qa + 8*144);
            a[2] = *(const uint32_t*)(qa + 16);
            a[3] = *(const uint32_t*)(qa + 8*144 + 16);
#pragma unroll
            for (int j = 0; j < 8; j++) {
                const char* bp = kbp + (j*8 + gid)*144 + kc*32 + tig*4;
                uint32_t bfg[2] = { *(const uint32_t*)bp, *(const uint32_t*)(bp + 16) };
                mma_f16(s[j], a, bfg);
            }
        }
        float mt0 = -1e30f, mt1 = -1e30f;
#pragma unroll
        for (int j = 0; j < 8; j++) {
            s[j][0] *= 0.125f; s[j][1] *= 0.125f; s[j][2] *= 0.125f; s[j][3] *= 0.125f;
            mt0 = fmaxf(mt0, fmaxf(s[j][0], s[j][1]));
            mt1 = fmaxf(mt1, fmaxf(s[j][2], s[j][3]));
        }
        mt0 = fmaxf(mt0, __shfl_xor_sync(0xffffffffu, mt0, 1));
        mt0 = fmaxf(mt0, __shfl_xor_sync(0xffffffffu, mt0, 2));
        mt1 = fmaxf(mt1, __shfl_xor_sync(0xffffffffu, mt1, 1));
        mt1 = fmaxf(mt1, __shfl_xor_sync(0xffffffffu, mt1, 2));
        float mn0 = fmaxf(m0, mt0), mn1 = fmaxf(m1, mt1);
        float al0 = __expf(m0 - mn0), al1 = __expf(m1 - mn1);
        float r0 = 0.f, r1 = 0.f;
#pragma unroll
        for (int j = 0; j < 8; j++) {
            s[j][0] = __expf(s[j][0] - mn0); s[j][1] = __expf(s[j][1] - mn0);
            s[j][2] = __expf(s[j][2] - mn1); s[j][3] = __expf(s[j][3] - mn1);
            r0 += s[j][0] + s[j][1];
            r1 += s[j][2] + s[j][3];
        }
        r0 += __shfl_xor_sync(0xffffffffu, r0, 1); r0 += __shfl_xor_sync(0xffffffffu, r0, 2);
        r1 += __shfl_xor_sync(0xffffffffu, r1, 1); r1 += __shfl_xor_sync(0xffffffffu, r1, 2);
        l0 = l0 * al0 + r0; l1 = l1 * al1 + r1;
        m0 = mn0; m1 = mn1;
#pragma unroll
        for (int nj = 0; nj < 8; nj++) {
            o[nj][0] *= al0; o[nj][1] *= al0; o[nj][2] *= al1; o[nj][3] *= al1;
        }
        uint32_t ap[4][4];
#pragma unroll
        for (int kc = 0; kc < 4; kc++) {
            ap[kc][0] = pack_h2(s[2*kc][0],   s[2*kc][1]);
            ap[kc][1] = pack_h2(s[2*kc][2],   s[2*kc][3]);
            ap[kc][2] = pack_h2(s[2*kc+1][0], s[2*kc+1][1]);
            ap[kc][3] = pack_h2(s[2*kc+1][2], s[2*kc+1][3]);
        }
#pragma unroll
        for (int nj = 0; nj < 8; nj++) {
#pragma unroll
            for (int kc = 0; kc < 4; kc++) {
                uint32_t addr = vb + (uint32_t)((kc*16 + (lane & 15))*144 + nj*16);
                uint32_t bv0, bv1;
                asm volatile("ldmatrix.sync.aligned.m8n8.x2.trans.shared.b16 {%0,%1}, [%2];"
                             : "=r"(bv0), "=r"(bv1) : "r"(addr));
                uint32_t bv[2] = { bv0, bv1 };
                mma_f16(o[nj], ap[kc], bv);
            }
        }
    }

    float il0 = 1.f / l0, il1 = 1.f / l1;
    size_t row0 = (size_t)(b*S_ + qt*128 + wq + gid);
#pragma unroll
    for (int nj = 0; nj < 8; nj++) {
        int col = h*DH + nj*8 + 2*tig;
        *(__half2*)&ao[row0*D_ + col]     = __floats2half2_rn(o[nj][0]*il0, o[nj][1]*il0);
        *(__half2*)&ao[(row0+8)*D_ + col] = __floats2half2_rn(o[nj][2]*il1, o[nj][3]*il1);
    }
}

// ---------------- weight preprocessing (convert to fp16) ----------------
__global__ void h_round_kernel(const float* __restrict__ w, __half* __restrict__ o, int n) {
    int i = blockIdx.x * 256 + threadIdx.x;
    if (i < n) o[i] = __float2half_rn(w[i]);
}
__global__ void h_tround_kernel(const float* __restrict__ w, __half* __restrict__ o, int R, int C) {
    __shared__ float t[32][33];
    int e = blockIdx.z;
    int r0 = blockIdx.y * 32, c0 = blockIdx.x * 32;
    const float* we = w + (size_t)e * R * C;
    int x = threadIdx.x, y = threadIdx.y;
#pragma unroll
    for (int i = 0; i < 32; i += 8)
        t[y + i][x] = we[(size_t)(r0 + y + i) * C + c0 + x];
    __syncthreads();
    size_t base = (size_t)e * R * C;
#pragma unroll
    for (int i = 0; i < 32; i += 8)
        o[base + (size_t)(c0 + y + i) * R + r0 + x] = __float2half_rn(t[x][y + i]);
}

// ---------------- LayerNorm ----------------
template<bool DUAL>
__global__ void ln_kernel(const float* __restrict__ x, const float* __restrict__ gam,
                          const float* __restrict__ bet, float* __restrict__ out_f,
                          __half* __restrict__ out_h) {
    int row = blockIdx.x;
    const float* xr = x + (size_t)row * D_;
    float v[3];
    float s = 0.f, s2 = 0.f;
#pragma unroll
    for (int i = 0; i < 3; i++) {
        v[i] = xr[threadIdx.x + i*256];
        s += v[i]; s2 += v[i]*v[i];
    }
    __shared__ float sh[16];
#pragma unroll
    for (int o = 16; o > 0; o >>= 1) {
        s  += __shfl_down_sync(0xffffffffu, s,  o);
        s2 += __shfl_down_sync(0xffffffffu, s2, o);
    }
    int w = threadIdx.x >> 5, l = threadIdx.x & 31;
    if (l == 0) { sh[w] = s; sh[w+8] = s2; }
    __syncthreads();
    if (threadIdx.x < 32) {
        float a  = (l < 8) ? sh[l]   : 0.f;
        float b2 = (l < 8) ? sh[l+8] : 0.f;
#pragma unroll
        for (int o = 4; o > 0; o >>= 1) {
            a  += __shfl_down_sync(0xffffffffu, a,  o);
            b2 += __shfl_down_sync(0xffffffffu, b2, o);
        }
        if (l == 0) { sh[0] = a; sh[1] = b2; }
    }
    __syncthreads();
    float mean = sh[0] * (1.f/D_);
    float var  = sh[1] * (1.f/D_) - mean*mean;
    float inv  = rsqrtf(var + 1e-5f);
#pragma unroll
    for (int i = 0; i < 3; i++) {
        int c = threadIdx.x + i*256;
        float r = (v[i] - mean) * inv * gam[c] + bet[c];
        if (DUAL) out_f[(size_t)row*D_ + c] = r;   // full precision for router
        out_h[(size_t)row*D_ + c] = __float2half_rn(r);
    }
}

// ---------------- MoE routing ----------------
__global__ void moe_init_kernel() {
    int i = blockIdx.x * blockDim.x + threadIdx.x;
    if (i < E_) g_cnt[i] = 0;
    if (i < MAX_ROWS) g_rowidx[i] = -1;
}

__global__ void router_kernel(const float* __restrict__ xm, const float* __restrict__ rw,
                              const float* __restrict__ rb)
{
    int t = blockIdx.x;
    int w = threadIdx.x >> 5, l = threadIdx.x & 31;
    const float* xr = xm + (size_t)t * D_;
    const float* wr = rw + (size_t)w * D_;
    float s = 0.f;
    for (int d = l; d < D_; d += 32) s += xr[d] * wr[d];
#pragma unroll
    for (int o = 16; o > 0; o >>= 1) s += __shfl_down_sync(0xffffffffu, s, o);
    __shared__ float sh[E_];
    if (l == 0) sh[w] = s + rb[w];
    __syncthreads();
    if (threadIdx.x == 0) {
        int e1 = 0; float l1 = sh[0];
        for (int e = 1; e < E_; e++) if (sh[e] > l1) { l1 = sh[e]; e1 = e; }
        int e2 = -1; float l2 = -1e30f;
        for (int e = 0; e < E_; e++) if (e != e1 && sh[e] > l2) { l2 = sh[e]; e2 = e; }
        float w1 = 1.f / (1.f + __expf(l2 - l1));
        g_topi[2*t] = e1; g_topi[2*t+1] = e2;
        g_topw[2*t] = w1; g_topw[2*t+1] = 1.f - w1;
        atomicAdd(&g_cnt[e1], 1);
        atomicAdd(&g_cnt[e2], 1);
    }
}

__global__ void scan_kernel() {
    if (threadIdx.x == 0) {
        int o = 0;
        for (int e = 0; e < E_; e++) {
            g_off[e] = o; g_cursor[e] = o;
            o += ((g_cnt[e] + 127) >> 7) << 7;
        }
        g_off[E_] = o;
    }
    __syncthreads();
    for (int t = threadIdx.x; t < MAX_TILES; t += blockDim.x) {
        int row = t << 7;
        int e = -1;
        for (int ee = 0; ee < E_; ee++)
            if (row >= g_off[ee] && row < g_off[ee+1]) e = ee;
        g_tile_e[t] = (row < g_off[E_]) ? e : -1;
    }
}

__global__ void assign_kernel() {
    int t = blockIdx.x * blockDim.x + threadIdx.x;
    if (t >= T_) return;
#pragma unroll
    for (int k = 0; k < 2; k++) {
        int e = g_topi[2*t + k];
        int pos = atomicAdd(&g_cursor[e], 1);
        g_rowidx[pos] = t;
        g_rowwt[pos]  = g_topw[2*t + k];
        g_slot[2*t + k] = pos;
    }
}

__global__ void combine_kernel(float* __restrict__ out) {
    int i = blockIdx.x * blockDim.x + threadIdx.x;
    int t = i / D_;
    int d = i - t * D_;
    int s0 = g_slot[2*t], s1 = g_slot[2*t + 1];
    out[i] += g_rowwt[s0] * g_y[(size_t)s0 * D_ + d]
            + g_rowwt[s1] * g_y[(size_t)s1 * D_ + d];
}

// ---------------- launch ----------------
extern "C" void kernel_launch(void* const* d_in, const int* in_sizes, int n_in,
                              void* d_out, int out_size)
{
    const float* x          = (const float*)d_in[0];
    const float* ln1_g      = (const float*)d_in[1];
    const float* ln1_b      = (const float*)d_in[2];
    const float* in_proj_w  = (const float*)d_in[3];
    const float* in_proj_b  = (const float*)d_in[4];
    const float* out_proj_w = (const float*)d_in[5];
    const float* out_proj_b = (const float*)d_in[6];
    const float* ln2_g      = (const float*)d_in[7];
    const float* ln2_b      = (const float*)d_in[8];
    const float* router_w   = (const float*)d_in[9];
    const float* router_b   = (const float*)d_in[10];
    const float* w1         = (const float*)d_in[11];
    const float* b1         = (const float*)d_in[12];
    const float* w2         = (const float*)d_in[13];
    const float* b2         = (const float*)d_in[14];
    float* out = (float*)d_out;

    float *p_xm, *p_y;
    __half *p_x2h, *p_qkvh, *p_aoh, *p_xmrh, *p_hh;
    cudaGetSymbolAddress((void**)&p_x2h,    g_x2h);
    cudaGetSymbolAddress((void**)&p_qkvh,   g_qkvh);
    cudaGetSymbolAddress((void**)&p_aoh,    g_aoh);
    cudaGetSymbolAddress((void**)&p_xm,     g_xm);
    cudaGetSymbolAddress((void**)&p_xmrh,   g_xmrh);
    cudaGetSymbolAddress((void**)&p_hh,     g_hh);
    cudaGetSymbolAddress((void**)&p_y,      g_y);
    __half *p_qw, *p_ow, *p_w1t, *p_w2t;
    cudaGetSymbolAddress((void**)&p_qw,  g_qkvw_h);
    cudaGetSymbolAddress((void**)&p_ow,  g_ow_h);
    cudaGetSymbolAddress((void**)&p_w1t, g_w1t_h);
    cudaGetSymbolAddress((void**)&p_w2t, g_w2t_h);

    cudaFuncSetAttribute(ca_gemm<false, false, 0, true >, cudaFuncAttributeMaxDynamicSharedMemorySize, CA_SMEM);
    cudaFuncSetAttribute(ca_gemm<false, false, 1, false>, cudaFuncAttributeMaxDynamicSharedMemorySize, CA_SMEM);
    cudaFuncSetAttribute(ca_gemm<true,  true,  2, true >, cudaFuncAttributeMaxDynamicSharedMemorySize, CA_SMEM);
    cudaFuncSetAttribute(ca_gemm<true,  false, 0, false>, cudaFuncAttributeMaxDynamicSharedMemorySize, CA_SMEM);
    cudaFuncSetAttribute(flash_kernel, cudaFuncAttributeMaxDynamicSharedMemorySize, FL_SMEM);

    // 0. weight preprocessing (fp16 convert; transpose MoE weights to [N,K])
    h_round_kernel<<<(NQKV*D_ + 255)/256, 256>>>(in_proj_w, p_qw, NQKV*D_);
    h_round_kernel<<<(D_*D_ + 255)/256, 256>>>(out_proj_w, p_ow, D_*D_);
    h_tround_kernel<<<dim3(DFF/32, D_/32, E_), dim3(32, 8)>>>(w1, p_w1t, D_, DFF);
    h_tround_kernel<<<dim3(D_/32, DFF/32, E_), dim3(32, 8)>>>(w2, p_w2t, DFF, D_);

    // 1. LN1 -> fp16
    ln_kernel<false><<<T_, 256>>>(x, ln1_g, ln1_b, nullptr, p_x2h);

    // 2. QKV projection (fp16 mma) -> fp16 qkv
    ca_gemm<false, false, 0, true><<<dim3(NQKV/256, T_/128), 256, CA_SMEM>>>(
        p_x2h, D_, p_qw, 0, in_proj_b, 0, nullptr, p_qkvh, NQKV, D_);

    // 3-5. fused flash attention -> fp16 ao
    flash_kernel<<<dim3(S_/128, B_*H_), 256, FL_SMEM>>>(p_qkvh, p_aoh);

    // 6. out-proj + bias + residual (fp16 mma) -> fp32 out
    ca_gemm<false, false, 1, false><<<dim3(D_/256, T_/128), 256, CA_SMEM>>>(
        p_aoh, D_, p_ow, 0, out_proj_b, 0, x, out, D_, D_);

    // 7. LN2: FULL fp32 xm (router) + fp16 xmrh (MoE1 A)
    ln_kernel<true><<<T_, 256>>>(out, ln2_g, ln2_b, p_xm, p_xmrh);

    // 8. routing (full-precision xm)
    moe_init_kernel<<<(MAX_ROWS + 255)/256, 256>>>();
    router_kernel<<<T_, 256>>>(p_xm, router_w, router_b);
    scan_kernel<<<1, 256>>>();
    assign_kernel<<<(T_ + 255)/256, 256>>>();

    // 9. MoE GEMM1: h = gelu(gather(xmrh) @ w1t[e]^T + b1[e]) -> fp16 h
    ca_gemm<true, true, 2, true><<<dim3(DFF/256, MAX_TILES), 256, CA_SMEM>>>(
        p_xmrh, D_, p_w1t, (long long)DFF*D_, b1, DFF, nullptr, p_hh, DFF, D_);

    // 10. MoE GEMM2: y = h @ w2t[e]^T + b2[e] -> fp32 y
    ca_gemm<true, false, 0, false><<<dim3(D_/256, MAX_TILES), 256, CA_SMEM>>>(
        p_hh, DFF, p_w2t, (long long)D_*DFF, b2, D_, nullptr, p_y, D_, DFF);

    // 11. combine
    combine_kernel<<<(T_*D_)/256, 256>>>(out);
}